// round 1
// baseline (speedup 1.0000x reference)
#include <cuda_runtime.h>
#include <cstdint>

#define MDIM 2048
#define NDIM 11264
#define KDIM 2048
#define LNUM 16
#define RNK 16
#define HALF_N 5632

// ---------------- device scratch (static, no allocation) ----------------
__device__ float g_xt[(size_t)MDIM * KDIM];   // tf32-converted x   (16 MB)
__device__ float g_wt[(size_t)NDIM * KDIM];   // tf32-converted W   (92 MB)
__device__ float g_xa[MDIM * 32];             // xa = x @ A[l]      (256 KB)
__device__ int   g_cnt[LNUM];
__device__ int   g_list[LNUM * MDIM];
__device__ int   g_is64;

__device__ __forceinline__ int load_idx(const int* p, int t) {
    return g_is64 ? p[2 * t] : p[t];
}

// ---------------- 0) dtype detect + counter zero ----------------
__global__ void k_detect(const int* __restrict__ idxp, int n) {
    __shared__ int sbad;
    if (threadIdx.x == 0) sbad = 0;
    __syncthreads();
    int bad = 0;
    // sample first n/2 entries: indices up to n-1 are in-bounds for both dtypes
    for (int i = threadIdx.x; i < n / 2; i += blockDim.x)
        if (idxp[2 * i + 1] != 0) bad = 1;
    if (bad) atomicExch(&sbad, 1);
    __syncthreads();
    if (threadIdx.x == 0) g_is64 = sbad ? 0 : 1;
    if (threadIdx.x < LNUM) g_cnt[threadIdx.x] = 0;
}

// ---------------- 1) fp32 -> tf32 convert ----------------
__device__ __forceinline__ float to_tf32(float v) {
    uint32_t o;
    asm("cvt.rna.tf32.f32 %0, %1;" : "=r"(o) : "f"(v));
    return __uint_as_float(o);
}

__global__ void k_convert(const float* __restrict__ src, int which, size_t n4) {
    float* dst = which ? g_wt : g_xt;
    size_t i = (size_t)blockIdx.x * blockDim.x + threadIdx.x;
    size_t stride = (size_t)gridDim.x * blockDim.x;
    for (; i < n4; i += stride) {
        float4 v = ((const float4*)src)[i];
        v.x = to_tf32(v.x); v.y = to_tf32(v.y);
        v.z = to_tf32(v.z); v.w = to_tf32(v.w);
        ((float4*)dst)[i] = v;
    }
}

// ---------------- 2) xa[t, 0:32] = sum_d x[t,d] * A[l, d, 0:32] ----------------
__global__ __launch_bounds__(256) void k_xa(const float* __restrict__ x,
                                            const float* __restrict__ A,
                                            const int* __restrict__ idxp) {
    int t = blockIdx.x;
    int l = load_idx(idxp, t);
    const float* xr = x + (size_t)t * KDIM;
    const float* Al = A + (size_t)l * KDIM * 32;

    float acc[32];
#pragma unroll
    for (int c = 0; c < 32; c++) acc[c] = 0.f;

    for (int d = threadIdx.x; d < KDIM; d += 256) {
        float xv = xr[d];
        const float4* Ar = (const float4*)(Al + (size_t)d * 32);
#pragma unroll
        for (int q = 0; q < 8; q++) {
            float4 v = Ar[q];
            acc[q * 4 + 0] += xv * v.x;
            acc[q * 4 + 1] += xv * v.y;
            acc[q * 4 + 2] += xv * v.z;
            acc[q * 4 + 3] += xv * v.w;
        }
    }
#pragma unroll
    for (int c = 0; c < 32; c++) {
#pragma unroll
        for (int off = 16; off > 0; off >>= 1)
            acc[c] += __shfl_xor_sync(0xffffffffu, acc[c], off);
    }
    __shared__ float red[8][32];
    int w = threadIdx.x >> 5, lane = threadIdx.x & 31;
    if (lane == 0) {
#pragma unroll
        for (int c = 0; c < 32; c++) red[w][c] = acc[c];
    }
    __syncthreads();
    if (threadIdx.x < 32) {
        float s = 0.f;
#pragma unroll
        for (int w2 = 0; w2 < 8; w2++) s += red[w2][threadIdx.x];
        g_xa[t * 32 + threadIdx.x] = s;
    }
}

// ---------------- 3) group tokens by expert index ----------------
__global__ void k_group(const int* __restrict__ idxp) {
    int t = blockIdx.x * blockDim.x + threadIdx.x;
    if (t < MDIM) {
        int l = load_idx(idxp, t);
        int pos = atomicAdd(&g_cnt[l], 1);
        g_list[l * MDIM + pos] = t;
    }
}

// ---------------- 4) TF32 tensor-core GEMM: out = x @ W^T ----------------
// 128x128 block tile, BK=32, 8 warps (2 x 4), warp tile 64x32 of m16n8k8.
__global__ __launch_bounds__(256, 1) void k_gemm(float* __restrict__ out) {
    __shared__ float xs[128][36];   // pitch 36 -> conflict-free fragment loads
    __shared__ float ws[128][36];

    const int tid = threadIdx.x;
    const int m0 = blockIdx.x * 128;   // m-fast block order => W tiles L2-reused
    const int n0 = blockIdx.y * 128;
    const int wid = tid >> 5;
    const int lane = tid & 31;
    const int wm = (wid & 1) * 64;
    const int wn = (wid >> 1) * 32;
    const int g = lane >> 2;     // 0..7
    const int tg = lane & 3;     // 0..3

    const int lrow = tid >> 3;        // 0..31
    const int lq = (tid & 7) * 4;     // 0,4,...,28

    float c[4][4][4];
#pragma unroll
    for (int i = 0; i < 4; i++)
#pragma unroll
        for (int j = 0; j < 4; j++)
#pragma unroll
            for (int k = 0; k < 4; k++) c[i][j][k] = 0.f;

    float4 rx[4], rw[4];
    const float* Ag = g_xt + (size_t)m0 * KDIM;
    const float* Bg = g_wt + (size_t)n0 * KDIM;

    auto load_g = [&](int k0) {
#pragma unroll
        for (int p = 0; p < 4; p++) {
            int r = lrow + p * 32;
            rx[p] = *(const float4*)(Ag + (size_t)r * KDIM + k0 + lq);
            rw[p] = *(const float4*)(Bg + (size_t)r * KDIM + k0 + lq);
        }
    };
    auto store_s = [&]() {
#pragma unroll
        for (int p = 0; p < 4; p++) {
            int r = lrow + p * 32;
            xs[r][lq + 0] = rx[p].x; xs[r][lq + 1] = rx[p].y;
            xs[r][lq + 2] = rx[p].z; xs[r][lq + 3] = rx[p].w;
            ws[r][lq + 0] = rw[p].x; ws[r][lq + 1] = rw[p].y;
            ws[r][lq + 2] = rw[p].z; ws[r][lq + 3] = rw[p].w;
        }
    };

    load_g(0);
    const int NST = KDIM / 32;
    for (int s = 0; s < NST; s++) {
        store_s();
        __syncthreads();
        if (s + 1 < NST) load_g((s + 1) * 32);   // LDG overlaps compute below

#pragma unroll
        for (int ks = 0; ks < 4; ks++) {
            const int kb = ks * 8;
            uint32_t a[4][4], b[4][2];
#pragma unroll
            for (int i = 0; i < 4; i++) {
                int mb = wm + i * 16;
                a[i][0] = __float_as_uint(xs[mb + g][kb + tg]);
                a[i][1] = __float_as_uint(xs[mb + g + 8][kb + tg]);
                a[i][2] = __float_as_uint(xs[mb + g][kb + tg + 4]);
                a[i][3] = __float_as_uint(xs[mb + g + 8][kb + tg + 4]);
            }
#pragma unroll
            for (int j = 0; j < 4; j++) {
                int nb = wn + j * 8;
                b[j][0] = __float_as_uint(ws[nb + g][kb + tg]);
                b[j][1] = __float_as_uint(ws[nb + g][kb + tg + 4]);
            }
#pragma unroll
            for (int i = 0; i < 4; i++)
#pragma unroll
                for (int j = 0; j < 4; j++) {
                    asm volatile(
                        "mma.sync.aligned.m16n8k8.row.col.f32.tf32.tf32.f32 "
                        "{%0,%1,%2,%3}, {%4,%5,%6,%7}, {%8,%9}, {%0,%1,%2,%3};\n"
                        : "+f"(c[i][j][0]), "+f"(c[i][j][1]),
                          "+f"(c[i][j][2]), "+f"(c[i][j][3])
                        : "r"(a[i][0]), "r"(a[i][1]), "r"(a[i][2]), "r"(a[i][3]),
                          "r"(b[j][0]), "r"(b[j][1]));
                }
        }
        __syncthreads();
    }

#pragma unroll
    for (int i = 0; i < 4; i++) {
        int row0 = m0 + wm + i * 16 + g;
#pragma unroll
        for (int j = 0; j < 4; j++) {
            int col = n0 + wn + j * 8 + tg * 2;
            *(float2*)(out + (size_t)row0 * NDIM + col) =
                make_float2(c[i][j][0], c[i][j][1]);
            *(float2*)(out + (size_t)(row0 + 8) * NDIM + col) =
                make_float2(c[i][j][2], c[i][j][3]);
        }
    }
}

// ---------------- 5) rank-16 delta, grouped by expert ----------------
__global__ __launch_bounds__(128) void k_delta(const float* __restrict__ B,
                                               float* __restrict__ out) {
    int l = blockIdx.y;
    int n0 = blockIdx.x * 128;
    int h = (n0 >= HALF_N) ? 16 : 0;

    __shared__ float Bs[RNK][128];
    for (int i = threadIdx.x; i < RNK * 128; i += 128) {
        int r = i >> 7, cc = i & 127;
        Bs[r][cc] = B[((size_t)l * RNK + r) * NDIM + n0 + cc];
    }
    __syncthreads();

    int cnt = g_cnt[l];
    int c = threadIdx.x;
#pragma unroll 2
    for (int i = 0; i < cnt; i++) {
        int t = g_list[l * MDIM + i];
        const float* xr = g_xa + t * 32 + h;
        float acc = 0.f;
#pragma unroll
        for (int r = 0; r < RNK; r++) acc += xr[r] * Bs[r][c];
        size_t o = (size_t)t * NDIM + n0 + c;
        out[o] += acc;
    }
}

// ---------------- launch ----------------
extern "C" void kernel_launch(void* const* d_in, const int* in_sizes, int n_in,
                              void* d_out, int out_size) {
    const float* x = (const float*)d_in[0];
    const float* W = (const float*)d_in[1];
    const float* A = (const float*)d_in[2];
    const float* B = (const float*)d_in[3];
    const int* idxp = (const int*)d_in[4];   // int32 or int64 (detected)
    float* out = (float*)d_out;

    k_detect<<<1, 256>>>(idxp, MDIM);
    k_convert<<<4096, 256>>>(x, 0, (size_t)MDIM * KDIM / 4);
    k_convert<<<22528, 256>>>(W, 1, (size_t)NDIM * KDIM / 4);
    k_xa<<<MDIM, 256>>>(x, A, idxp);
    k_group<<<8, 256>>>(idxp);
    k_gemm<<<dim3(MDIM / 128, NDIM / 128), 256>>>(out);
    k_delta<<<dim3(NDIM / 128, LNUM), 128>>>(B, out);
}

// round 3
// speedup vs baseline: 1.0423x; 1.0423x over previous
#include <cuda_runtime.h>
#include <cstdint>

#define MDIM 2048
#define NDIM 11264
#define KDIM 2048
#define LNUM 16
#define RNK 16
#define HALF_N 5632

// GEMM tiling: CTA 128m x 256n, BK=32, 4-stage cp.async pipeline
#define TILE_M 128
#define TILE_N 256
#define NS (KDIM / 32)                 // 64 k-stages
#define STAGE_A (TILE_M * 32 * 4)      // 16384 B
#define STAGE_B (TILE_N * 32 * 4)      // 32768 B
#define STAGE_BYTES (STAGE_A + STAGE_B)  // 49152
#define NBUF 4
#define SMEM_DYN (NBUF * STAGE_BYTES)    // 196608

// ---------------- device scratch ----------------
// g_xt: fragment-permuted tf32 x. Tile = 16m x 8k = 128 floats, lane-ordered
//       float4 [A[g][tg], A[g+8][tg], A[g][tg+4], A[g+8][tg+4]].
//       offset(mt, kt) = (mt*256 + kt)*128 floats.
// g_wt: fragment-permuted tf32 W. Tile = 8n x 8k = 64 floats, lane-ordered
//       float2 [W[g][tg], W[g][tg+4]].  offset(nt, kt) = (nt*256 + kt)*64.
__device__ float g_xt[(size_t)MDIM * KDIM];
__device__ float g_wt[(size_t)NDIM * KDIM];
__device__ float g_xa[MDIM * 32];
__device__ int   g_cnt[LNUM];
__device__ int   g_list[LNUM * MDIM];
__device__ int   g_is64;

__device__ __forceinline__ int load_idx(const int* p, int t) {
    return g_is64 ? p[2 * t] : p[t];
}

// ---------------- helpers ----------------
__device__ __forceinline__ uint32_t smem_u32(const void* p) {
    uint32_t a;
    asm("{ .reg .u64 t; cvta.to.shared.u64 t, %1; cvt.u32.u64 %0, t; }" : "=r"(a) : "l"(p));
    return a;
}
__device__ __forceinline__ void cpasync16(uint32_t dst, const void* src) {
    asm volatile("cp.async.cg.shared.global [%0], [%1], 16;" :: "r"(dst), "l"(src));
}
__device__ __forceinline__ void cp_commit() {
    asm volatile("cp.async.commit_group;" ::: "memory");
}
template <int N> __device__ __forceinline__ void cp_wait() {
    asm volatile("cp.async.wait_group %0;" :: "n"(N) : "memory");
}
__device__ __forceinline__ float to_tf32(float v) {
    uint32_t o;
    asm("cvt.rna.tf32.f32 %0, %1;" : "=r"(o) : "f"(v));
    return __uint_as_float(o);
}

// ---------------- 0) dtype detect + counter zero ----------------
__global__ void k_detect(const int* __restrict__ idxp, int n) {
    __shared__ int sbad;
    if (threadIdx.x == 0) sbad = 0;
    __syncthreads();
    int bad = 0;
    for (int i = threadIdx.x; i < n / 2; i += blockDim.x)
        if (idxp[2 * i + 1] != 0) bad = 1;
    if (bad) atomicExch(&sbad, 1);
    __syncthreads();
    if (threadIdx.x == 0) g_is64 = sbad ? 0 : 1;
    if (threadIdx.x < LNUM) g_cnt[threadIdx.x] = 0;
}

// ---------------- 1) group tokens by expert ----------------
__global__ void k_group(const int* __restrict__ idxp) {
    int t = blockIdx.x * blockDim.x + threadIdx.x;
    if (t < MDIM) {
        int l = load_idx(idxp, t);
        int pos = atomicAdd(&g_cnt[l], 1);
        g_list[l * MDIM + pos] = t;
    }
}

// ---------------- 2) convert x -> fragment-permuted tf32 ----------------
// block: 16 rows x 256 cols slab.  grid: (MDIM/16, KDIM/256)
__global__ __launch_bounds__(256) void k_convx(const float* __restrict__ x) {
    __shared__ float s[16][260];
    const int tid = threadIdx.x;
    const int m0 = blockIdx.x * 16, k0 = blockIdx.y * 256;
#pragma unroll
    for (int p = 0; p < 4; p++) {
        int idx = tid + p * 256;
        int row = idx >> 6, c4 = (idx & 63) * 4;
        float4 v = *(const float4*)(x + (size_t)(m0 + row) * KDIM + k0 + c4);
        s[row][c4] = v.x; s[row][c4 + 1] = v.y; s[row][c4 + 2] = v.z; s[row][c4 + 3] = v.w;
    }
    __syncthreads();
    const int w = tid >> 5, lane = tid & 31;
    const int g = lane >> 2, tg = lane & 3;
#pragma unroll
    for (int q = 0; q < 4; q++) {
        int kt = w * 4 + q;
        int kc = kt * 8;
        float4 o = make_float4(to_tf32(s[g][kc + tg]), to_tf32(s[g + 8][kc + tg]),
                               to_tf32(s[g][kc + tg + 4]), to_tf32(s[g + 8][kc + tg + 4]));
        size_t dst = ((size_t)blockIdx.x * 256 + blockIdx.y * 32 + kt) * 128 + lane * 4;
        *(float4*)(g_xt + dst) = o;
    }
}

// ---------------- 3) convert W -> fragment-permuted tf32 ----------------
// block: 16 n-rows (2 n-tiles) x 256 cols.  grid: (NDIM/16, KDIM/256)
__global__ __launch_bounds__(256) void k_convw(const float* __restrict__ W) {
    __shared__ float s[16][260];
    const int tid = threadIdx.x;
    const int n0 = blockIdx.x * 16, k0 = blockIdx.y * 256;
#pragma unroll
    for (int p = 0; p < 4; p++) {
        int idx = tid + p * 256;
        int row = idx >> 6, c4 = (idx & 63) * 4;
        float4 v = *(const float4*)(W + (size_t)(n0 + row) * KDIM + k0 + c4);
        s[row][c4] = v.x; s[row][c4 + 1] = v.y; s[row][c4 + 2] = v.z; s[row][c4 + 3] = v.w;
    }
    __syncthreads();
    const int w = tid >> 5, lane = tid & 31;
    const int g = lane >> 2, tg = lane & 3;
#pragma unroll
    for (int q = 0; q < 4; q++) {
        int kt = w * 4 + q;
        int kc = kt * 8;
#pragma unroll
        for (int nsub = 0; nsub < 2; nsub++) {
            float2 o = make_float2(to_tf32(s[nsub * 8 + g][kc + tg]),
                                   to_tf32(s[nsub * 8 + g][kc + tg + 4]));
            size_t dst = ((size_t)(blockIdx.x * 2 + nsub) * 256 + blockIdx.y * 32 + kt) * 64 +
                         lane * 2;
            *(float2*)(g_wt + dst) = o;
        }
    }
}

// ---------------- 4) xa, expert-grouped, A chunk in smem ----------------
__global__ __launch_bounds__(256) void k_xa2(const float* __restrict__ x,
                                             const float* __restrict__ A) {
    __shared__ float As[128][33];
    __shared__ float xs[32][128];
    __shared__ int stok[32];
    const int l = blockIdx.y;
    const int cnt = g_cnt[l];
    const int tid = threadIdx.x, w = tid >> 5, lane = tid & 31;

    for (int ibase = blockIdx.x * 32; ibase < cnt; ibase += gridDim.x * 32) {
        if (tid < 32)
            stok[tid] = (ibase + tid < cnt) ? g_list[l * MDIM + ibase + tid] : -1;
        __syncthreads();
        float acc[4] = {0.f, 0.f, 0.f, 0.f};
        for (int ch = 0; ch < KDIM / 128; ch++) {
            const int d0 = ch * 128;
#pragma unroll
            for (int j = 0; j < 16; j++) {
                int idx = tid + j * 256;
                int dd = idx >> 5, c = idx & 31;
                As[dd][c] = A[((size_t)l * KDIM + d0 + dd) * 32 + c];
            }
#pragma unroll
            for (int j = 0; j < 16; j++) {
                int idx = tid + j * 256;
                int slot = idx >> 7, dd = idx & 127;
                int t = stok[slot];
                xs[slot][dd] = (t >= 0) ? x[(size_t)t * KDIM + d0 + dd] : 0.f;
            }
            __syncthreads();
            const float4* xv0 = (const float4*)xs[w * 4 + 0];
            const float4* xv1 = (const float4*)xs[w * 4 + 1];
            const float4* xv2 = (const float4*)xs[w * 4 + 2];
            const float4* xv3 = (const float4*)xs[w * 4 + 3];
#pragma unroll
            for (int q = 0; q < 32; q++) {
                float a0 = As[q * 4 + 0][lane];
                float a1 = As[q * 4 + 1][lane];
                float a2 = As[q * 4 + 2][lane];
                float a3 = As[q * 4 + 3][lane];
                float4 v0 = xv0[q], v1 = xv1[q], v2 = xv2[q], v3 = xv3[q];
                acc[0] += v0.x * a0 + v0.y * a1 + v0.z * a2 + v0.w * a3;
                acc[1] += v1.x * a0 + v1.y * a1 + v1.z * a2 + v1.w * a3;
                acc[2] += v2.x * a0 + v2.y * a1 + v2.z * a2 + v2.w * a3;
                acc[3] += v3.x * a0 + v3.y * a1 + v3.z * a2 + v3.w * a3;
            }
            __syncthreads();
        }
#pragma unroll
        for (int tk = 0; tk < 4; tk++) {
            int t = stok[w * 4 + tk];
            if (t >= 0) g_xa[t * 32 + lane] = acc[tk];
        }
        __syncthreads();
    }
}

// ---------------- 5) TF32 mma.sync GEMM: out = x @ W^T ----------------
__global__ __launch_bounds__(256, 1) void k_gemm(float* __restrict__ out) {
    extern __shared__ char dyn[];
    const uint32_t dbase = smem_u32(dyn);

    const int tid = threadIdx.x;
    const int wid = tid >> 5;
    const int lane = tid & 31;
    const int mt0 = blockIdx.x * 8;    // 8 A-tiles of 16 rows
    const int nt0 = blockIdx.y * 32;   // 32 B-tiles of 8 cols
    const int mhalf = wid & 1;         // warp 64x64 tile
    const int nq = wid >> 1;

    const char* gA = (const char*)g_xt;
    const char* gB = (const char*)g_wt;

    auto issue_stage = [&](int s, int b) {
        const uint32_t abase = dbase + b * STAGE_BYTES;
        const uint32_t bbase = abase + STAGE_A;
        const int kt0 = s * 4;
#pragma unroll
        for (int j = 0; j < 4; j++) {
            int c = tid + j * 256;           // 0..1023 : A chunks
            int mtl = c >> 7, r = c & 127;
            const char* src = gA + ((size_t)(mt0 + mtl) * 256 + kt0) * 512 + r * 16;
            cpasync16(abase + mtl * 2048 + r * 16, src);
        }
#pragma unroll
        for (int j = 0; j < 8; j++) {
            int c = tid + j * 256;           // 0..2047 : B chunks
            int ntl = c >> 6, r = c & 63;
            const char* src = gB + ((size_t)(nt0 + ntl) * 256 + kt0) * 256 + r * 16;
            cpasync16(bbase + ntl * 1024 + r * 16, src);
        }
        cp_commit();
    };

    float c[4][8][4];
#pragma unroll
    for (int i = 0; i < 4; i++)
#pragma unroll
        for (int j = 0; j < 8; j++)
#pragma unroll
            for (int q = 0; q < 4; q++) c[i][j][q] = 0.f;

    issue_stage(0, 0);
    issue_stage(1, 1);
    issue_stage(2, 2);

#pragma unroll 1
    for (int s = 0; s < NS; s++) {
        if (s < NS - 2) cp_wait<2>();
        else if (s == NS - 2) cp_wait<1>();
        else cp_wait<0>();
        __syncthreads();

        if (s + 3 < NS) issue_stage(s + 3, (s + 3) & 3);

        const int b = s & 3;
        const uint32_t abase = dbase + b * STAGE_BYTES;
        const uint32_t bbase = abase + STAGE_A;
        const char* sa = dyn + (abase - dbase);
        const char* sb = dyn + (bbase - dbase);

#pragma unroll
        for (int ktl = 0; ktl < 4; ktl++) {
            uint4 a[4];
            uint2 bfr[8];
#pragma unroll
            for (int i = 0; i < 4; i++) {
                int mtl = mhalf * 4 + i;
                a[i] = *(const uint4*)(sa + mtl * 2048 + ktl * 512 + lane * 16);
            }
#pragma unroll
            for (int j = 0; j < 8; j++) {
                int ntl = nq * 8 + j;
                bfr[j] = *(const uint2*)(sb + ntl * 1024 + ktl * 256 + lane * 8);
            }
#pragma unroll
            for (int i = 0; i < 4; i++)
#pragma unroll
                for (int j = 0; j < 8; j++) {
                    asm volatile(
                        "mma.sync.aligned.m16n8k8.row.col.f32.tf32.tf32.f32 "
                        "{%0,%1,%2,%3}, {%4,%5,%6,%7}, {%8,%9}, {%0,%1,%2,%3};\n"
                        : "+f"(c[i][j][0]), "+f"(c[i][j][1]),
                          "+f"(c[i][j][2]), "+f"(c[i][j][3])
                        : "r"(a[i].x), "r"(a[i].y), "r"(a[i].z), "r"(a[i].w),
                          "r"(bfr[j].x), "r"(bfr[j].y));
                }
        }
    }

    // epilogue
    const int g = lane >> 2, tg = lane & 3;
    const int m0 = blockIdx.x * TILE_M, n0 = blockIdx.y * TILE_N;
#pragma unroll
    for (int i = 0; i < 4; i++) {
        int row0 = m0 + mhalf * 64 + i * 16 + g;
#pragma unroll
        for (int j = 0; j < 8; j++) {
            int col = n0 + nq * 64 + j * 8 + tg * 2;
            *(float2*)(out + (size_t)row0 * NDIM + col) = make_float2(c[i][j][0], c[i][j][1]);
            *(float2*)(out + (size_t)(row0 + 8) * NDIM + col) = make_float2(c[i][j][2], c[i][j][3]);
        }
    }
}

// ---------------- 6) rank-16 delta, grouped by expert ----------------
__global__ __launch_bounds__(128) void k_delta(const float* __restrict__ B,
                                               float* __restrict__ out) {
    int l = blockIdx.y;
    int n0 = blockIdx.x * 128;
    int h = (n0 >= HALF_N) ? 16 : 0;

    __shared__ float Bs[RNK][128];
    for (int i = threadIdx.x; i < RNK * 128; i += 128) {
        int r = i >> 7, cc = i & 127;
        Bs[r][cc] = B[((size_t)l * RNK + r) * NDIM + n0 + cc];
    }
    __syncthreads();

    int cnt = g_cnt[l];
    int c = threadIdx.x;
#pragma unroll 2
    for (int i = 0; i < cnt; i++) {
        int t = g_list[l * MDIM + i];
        const float* xr = g_xa + t * 32 + h;
        float acc = 0.f;
#pragma unroll
        for (int r = 0; r < RNK; r++) acc += xr[r] * Bs[r][c];
        size_t o = (size_t)t * NDIM + n0 + c;
        out[o] += acc;
    }
}

// ---------------- launch ----------------
extern "C" void kernel_launch(void* const* d_in, const int* in_sizes, int n_in,
                              void* d_out, int out_size) {
    const float* x = (const float*)d_in[0];
    const float* W = (const float*)d_in[1];
    const float* A = (const float*)d_in[2];
    const float* B = (const float*)d_in[3];
    const int* idxp = (const int*)d_in[4];
    float* out = (float*)d_out;

    cudaFuncSetAttribute(k_gemm, cudaFuncAttributeMaxDynamicSharedMemorySize, SMEM_DYN);

    k_detect<<<1, 256>>>(idxp, MDIM);
    k_group<<<8, 256>>>(idxp);
    k_convx<<<dim3(MDIM / 16, KDIM / 256), 256>>>(x);
    k_convw<<<dim3(NDIM / 16, KDIM / 256), 256>>>(W);
    k_xa2<<<dim3(4, LNUM), 256>>>(x, A);
    k_gemm<<<dim3(MDIM / TILE_M, NDIM / TILE_N), 256, SMEM_DYN>>>(out);
    k_delta<<<dim3(NDIM / 128, LNUM), 128>>>(B, out);
}

// round 4
// speedup vs baseline: 1.3429x; 1.2884x over previous
#include <cuda_runtime.h>
#include <cuda_fp16.h>
#include <cstdint>

#define MDIM 2048
#define NDIM 11264
#define KDIM 2048
#define LNUM 16
#define RNK 16
#define HALF_N 5632

// GEMM tiling: CTA 128m x 256n, fp16 m16n8k16, BK=64 (4 k-tiles of 16), 4-buf pipeline
#define TILE_M 128
#define TILE_N 256
#define NS (KDIM / 64)                   // 32 stages
#define STAGE_A (8 * 4 * 512)            // 16384 B  (8 m-tiles x 4 k-tiles x 512B)
#define STAGE_B (32 * 4 * 256)           // 32768 B  (32 n-tiles x 4 k-tiles x 256B)
#define STAGE_BYTES (STAGE_A + STAGE_B)
#define NBUF 4
#define SMEM_DYN (NBUF * STAGE_BYTES)    // 196608

#define KT (KDIM / 16)                   // 128 k-tiles total
#define XT_ROW (KT * 512)                // bytes per m-tile row in g_xt
#define WT_ROW (KT * 256)                // bytes per n-tile row in g_wt
#define WSCALE 256.0f
#define OSCALE 0.00390625f               // 1/256

// ---------------- device scratch ----------------
// g_xt: fragment-permuted fp16 x.  A-tile = 16m x 16k = 512 B; per lane uint4
//       {a0,a1,a2,a3} per m16n8k16 fp16 A layout.
// g_wt: fragment-permuted fp16 (256*W).  B-tile = 8n x 16k = 256 B; per lane
//       uint2 {b0,b1} per m16n8k16 fp16 B layout.
__device__ uint4 g_xt[(size_t)(MDIM / 16) * KT * 32];
__device__ uint2 g_wt[(size_t)(NDIM / 8) * KT * 32];
__device__ float g_xa[MDIM * 32];
__device__ int   g_cnt[LNUM];
__device__ int   g_list[LNUM * MDIM];
__device__ int   g_is64;

__device__ __forceinline__ int load_idx(const int* p, int t) {
    return g_is64 ? p[2 * t] : p[t];
}

// ---------------- helpers ----------------
__device__ __forceinline__ uint32_t smem_u32(const void* p) {
    uint32_t a;
    asm("{ .reg .u64 t; cvta.to.shared.u64 t, %1; cvt.u32.u64 %0, t; }" : "=r"(a) : "l"(p));
    return a;
}
__device__ __forceinline__ void cpasync16(uint32_t dst, const void* src) {
    asm volatile("cp.async.cg.shared.global [%0], [%1], 16;" :: "r"(dst), "l"(src));
}
__device__ __forceinline__ void cp_commit() {
    asm volatile("cp.async.commit_group;" ::: "memory");
}
template <int N> __device__ __forceinline__ void cp_wait() {
    asm volatile("cp.async.wait_group %0;" :: "n"(N) : "memory");
}
__device__ __forceinline__ uint32_t pack_h2(float lo, float hi) {
    __half2 h = __floats2half2_rn(lo, hi);
    return *(uint32_t*)&h;
}

// ---------------- 0) dtype detect + counter zero ----------------
__global__ void k_detect(const int* __restrict__ idxp, int n) {
    __shared__ int sbad;
    if (threadIdx.x == 0) sbad = 0;
    __syncthreads();
    int bad = 0;
    for (int i = threadIdx.x; i < n / 2; i += blockDim.x)
        if (idxp[2 * i + 1] != 0) bad = 1;
    if (bad) atomicExch(&sbad, 1);
    __syncthreads();
    if (threadIdx.x == 0) g_is64 = sbad ? 0 : 1;
    if (threadIdx.x < LNUM) g_cnt[threadIdx.x] = 0;
}

// ---------------- 1) group tokens by expert ----------------
__global__ void k_group(const int* __restrict__ idxp) {
    int t = blockIdx.x * blockDim.x + threadIdx.x;
    if (t < MDIM) {
        int l = load_idx(idxp, t);
        int pos = atomicAdd(&g_cnt[l], 1);
        g_list[l * MDIM + pos] = t;
    }
}

// ---------------- 2) convert x -> fragment-permuted fp16 ----------------
// block: 16 rows x 256 cols slab = 16 k-tiles; 8 warps x 2 tiles each.
__global__ __launch_bounds__(256) void k_convx(const float* __restrict__ x) {
    __shared__ float s[16][260];
    const int tid = threadIdx.x;
    const int mt = blockIdx.x;
    const int m0 = mt * 16, k0 = blockIdx.y * 256;
#pragma unroll
    for (int p = 0; p < 4; p++) {
        int idx = tid + p * 256;
        int row = idx >> 6, c4 = (idx & 63) * 4;
        float4 v = *(const float4*)(x + (size_t)(m0 + row) * KDIM + k0 + c4);
        s[row][c4] = v.x; s[row][c4 + 1] = v.y; s[row][c4 + 2] = v.z; s[row][c4 + 3] = v.w;
    }
    __syncthreads();
    const int w = tid >> 5, lane = tid & 31;
    const int g = lane >> 2, tg2 = (lane & 3) * 2;
#pragma unroll
    for (int q = 0; q < 2; q++) {
        int ktl = w * 2 + q;
        int kc = ktl * 16;
        uint32_t a0 = pack_h2(s[g][kc + tg2], s[g][kc + tg2 + 1]);
        uint32_t a1 = pack_h2(s[g + 8][kc + tg2], s[g + 8][kc + tg2 + 1]);
        uint32_t a2 = pack_h2(s[g][kc + tg2 + 8], s[g][kc + tg2 + 9]);
        uint32_t a3 = pack_h2(s[g + 8][kc + tg2 + 8], s[g + 8][kc + tg2 + 9]);
        int ktg = blockIdx.y * 16 + ktl;
        g_xt[((size_t)mt * KT + ktg) * 32 + lane] = make_uint4(a0, a1, a2, a3);
    }
}

// ---------------- 3) convert W -> fragment-permuted fp16 (scaled x256) ------
// block: 16 n-rows (2 n-tiles) x 256 cols; 8 warps x 2 k-tiles each.
__global__ __launch_bounds__(256) void k_convw(const float* __restrict__ W) {
    __shared__ float s[16][260];
    const int tid = threadIdx.x;
    const int n0 = blockIdx.x * 16, k0 = blockIdx.y * 256;
#pragma unroll
    for (int p = 0; p < 4; p++) {
        int idx = tid + p * 256;
        int row = idx >> 6, c4 = (idx & 63) * 4;
        float4 v = *(const float4*)(W + (size_t)(n0 + row) * KDIM + k0 + c4);
        s[row][c4] = v.x * WSCALE; s[row][c4 + 1] = v.y * WSCALE;
        s[row][c4 + 2] = v.z * WSCALE; s[row][c4 + 3] = v.w * WSCALE;
    }
    __syncthreads();
    const int w = tid >> 5, lane = tid & 31;
    const int g = lane >> 2, tg2 = (lane & 3) * 2;
#pragma unroll
    for (int q = 0; q < 2; q++) {
        int ktl = w * 2 + q;
        int kc = ktl * 16;
        int ktg = blockIdx.y * 16 + ktl;
#pragma unroll
        for (int nsub = 0; nsub < 2; nsub++) {
            uint32_t b0 = pack_h2(s[nsub * 8 + g][kc + tg2], s[nsub * 8 + g][kc + tg2 + 1]);
            uint32_t b1 = pack_h2(s[nsub * 8 + g][kc + tg2 + 8], s[nsub * 8 + g][kc + tg2 + 9]);
            int nt = blockIdx.x * 2 + nsub;
            g_wt[((size_t)nt * KT + ktg) * 32 + lane] = make_uint2(b0, b1);
        }
    }
}

// ---------------- 4) xa, expert-grouped, A chunk in smem ----------------
__global__ __launch_bounds__(256) void k_xa2(const float* __restrict__ x,
                                             const float* __restrict__ A) {
    __shared__ float As[128][33];
    __shared__ float xs[32][128];
    __shared__ int stok[32];
    const int l = blockIdx.y;
    const int cnt = g_cnt[l];
    const int tid = threadIdx.x, w = tid >> 5, lane = tid & 31;

    for (int ibase = blockIdx.x * 32; ibase < cnt; ibase += gridDim.x * 32) {
        if (tid < 32)
            stok[tid] = (ibase + tid < cnt) ? g_list[l * MDIM + ibase + tid] : -1;
        __syncthreads();
        float acc[4] = {0.f, 0.f, 0.f, 0.f};
        for (int ch = 0; ch < KDIM / 128; ch++) {
            const int d0 = ch * 128;
#pragma unroll
            for (int j = 0; j < 16; j++) {
                int idx = tid + j * 256;
                int dd = idx >> 5, c = idx & 31;
                As[dd][c] = A[((size_t)l * KDIM + d0 + dd) * 32 + c];
            }
#pragma unroll
            for (int j = 0; j < 16; j++) {
                int idx = tid + j * 256;
                int slot = idx >> 7, dd = idx & 127;
                int t = stok[slot];
                xs[slot][dd] = (t >= 0) ? x[(size_t)t * KDIM + d0 + dd] : 0.f;
            }
            __syncthreads();
            const float4* xv0 = (const float4*)xs[w * 4 + 0];
            const float4* xv1 = (const float4*)xs[w * 4 + 1];
            const float4* xv2 = (const float4*)xs[w * 4 + 2];
            const float4* xv3 = (const float4*)xs[w * 4 + 3];
#pragma unroll
            for (int q = 0; q < 32; q++) {
                float a0 = As[q * 4 + 0][lane];
                float a1 = As[q * 4 + 1][lane];
                float a2 = As[q * 4 + 2][lane];
                float a3 = As[q * 4 + 3][lane];
                float4 v0 = xv0[q], v1 = xv1[q], v2 = xv2[q], v3 = xv3[q];
                acc[0] += v0.x * a0 + v0.y * a1 + v0.z * a2 + v0.w * a3;
                acc[1] += v1.x * a0 + v1.y * a1 + v1.z * a2 + v1.w * a3;
                acc[2] += v2.x * a0 + v2.y * a1 + v2.z * a2 + v2.w * a3;
                acc[3] += v3.x * a0 + v3.y * a1 + v3.z * a2 + v3.w * a3;
            }
            __syncthreads();
        }
#pragma unroll
        for (int tk = 0; tk < 4; tk++) {
            int t = stok[w * 4 + tk];
            if (t >= 0) g_xa[t * 32 + lane] = acc[tk];
        }
        __syncthreads();
    }
}

// ---------------- 5) fp16 mma.sync GEMM: out = x @ W^T ----------------
__global__ __launch_bounds__(256, 1) void k_gemm(float* __restrict__ out) {
    extern __shared__ char dyn[];
    const uint32_t dbase = smem_u32(dyn);

    const int tid = threadIdx.x;
    const int wid = tid >> 5;
    const int lane = tid & 31;
    const int mt0 = blockIdx.x * 8;    // 8 m-tiles of 16 rows
    const int nt0 = blockIdx.y * 32;   // 32 n-tiles of 8 cols
    const int mhalf = wid & 1;         // warp tile 64m x 64n
    const int nq = wid >> 1;

    const char* gA = (const char*)g_xt;
    const char* gB = (const char*)g_wt;

    auto issue_stage = [&](int s, int b) {
        const uint32_t abase = dbase + b * STAGE_BYTES;
        const uint32_t bbase = abase + STAGE_A;
#pragma unroll
        for (int j = 0; j < 4; j++) {
            int c = tid + j * 256;           // 1024 A chunks of 16B
            int mtl = c >> 7, r = c & 127;   // 4 k-tiles x 32 chunks per m-tile
            const char* src = gA + (size_t)(mt0 + mtl) * XT_ROW + s * 2048 + r * 16;
            cpasync16(abase + mtl * 2048 + r * 16, src);
        }
#pragma unroll
        for (int j = 0; j < 8; j++) {
            int c = tid + j * 256;           // 2048 B chunks of 16B
            int ntl = c >> 6, r = c & 63;    // 4 k-tiles x 16 chunks per n-tile
            const char* src = gB + (size_t)(nt0 + ntl) * WT_ROW + s * 1024 + r * 16;
            cpasync16(bbase + ntl * 1024 + r * 16, src);
        }
        cp_commit();
    };

    float c[4][8][4];
#pragma unroll
    for (int i = 0; i < 4; i++)
#pragma unroll
        for (int j = 0; j < 8; j++)
#pragma unroll
            for (int q = 0; q < 4; q++) c[i][j][q] = 0.f;

    issue_stage(0, 0);
    issue_stage(1, 1);
    issue_stage(2, 2);

#pragma unroll 1
    for (int s = 0; s < NS; s++) {
        if (s < NS - 2) cp_wait<2>();
        else if (s == NS - 2) cp_wait<1>();
        else cp_wait<0>();
        __syncthreads();

        if (s + 3 < NS) issue_stage(s + 3, (s + 3) & 3);

        const int b = s & 3;
        const char* sa = dyn + b * STAGE_BYTES;
        const char* sb = sa + STAGE_A;

#pragma unroll
        for (int ktl = 0; ktl < 4; ktl++) {
            uint4 a[4];
            uint2 bfr[8];
#pragma unroll
            for (int i = 0; i < 4; i++) {
                int mtl = mhalf * 4 + i;
                a[i] = *(const uint4*)(sa + mtl * 2048 + ktl * 512 + lane * 16);
            }
#pragma unroll
            for (int j = 0; j < 8; j++) {
                int ntl = nq * 8 + j;
                bfr[j] = *(const uint2*)(sb + ntl * 1024 + ktl * 256 + lane * 8);
            }
#pragma unroll
            for (int i = 0; i < 4; i++)
#pragma unroll
                for (int j = 0; j < 8; j++) {
                    asm volatile(
                        "mma.sync.aligned.m16n8k16.row.col.f32.f16.f16.f32 "
                        "{%0,%1,%2,%3}, {%4,%5,%6,%7}, {%8,%9}, {%0,%1,%2,%3};\n"
                        : "+f"(c[i][j][0]), "+f"(c[i][j][1]),
                          "+f"(c[i][j][2]), "+f"(c[i][j][3])
                        : "r"(a[i].x), "r"(a[i].y), "r"(a[i].z), "r"(a[i].w),
                          "r"(bfr[j].x), "r"(bfr[j].y));
                }
        }
    }

    // epilogue (undo the x256 W scaling)
    const int g = lane >> 2, tg = lane & 3;
    const int m0 = blockIdx.x * TILE_M, n0 = blockIdx.y * TILE_N;
#pragma unroll
    for (int i = 0; i < 4; i++) {
        int row0 = m0 + mhalf * 64 + i * 16 + g;
#pragma unroll
        for (int j = 0; j < 8; j++) {
            int col = n0 + nq * 64 + j * 8 + tg * 2;
            *(float2*)(out + (size_t)row0 * NDIM + col) =
                make_float2(c[i][j][0] * OSCALE, c[i][j][1] * OSCALE);
            *(float2*)(out + (size_t)(row0 + 8) * NDIM + col) =
                make_float2(c[i][j][2] * OSCALE, c[i][j][3] * OSCALE);
        }
    }
}

// ---------------- 6) rank-16 delta, grouped by expert ----------------
__global__ __launch_bounds__(128) void k_delta(const float* __restrict__ B,
                                               float* __restrict__ out) {
    int l = blockIdx.y;
    int n0 = blockIdx.x * 128;
    int h = (n0 >= HALF_N) ? 16 : 0;

    __shared__ float Bs[RNK][128];
    for (int i = threadIdx.x; i < RNK * 128; i += 128) {
        int r = i >> 7, cc = i & 127;
        Bs[r][cc] = B[((size_t)l * RNK + r) * NDIM + n0 + cc];
    }
    __syncthreads();

    int cnt = g_cnt[l];
    int c = threadIdx.x;
#pragma unroll 2
    for (int i = 0; i < cnt; i++) {
        int t = g_list[l * MDIM + i];
        const float* xr = g_xa + t * 32 + h;
        float acc = 0.f;
#pragma unroll
        for (int r = 0; r < RNK; r++) acc += xr[r] * Bs[r][c];
        size_t o = (size_t)t * NDIM + n0 + c;
        out[o] += acc;
    }
}

// ---------------- launch ----------------
extern "C" void kernel_launch(void* const* d_in, const int* in_sizes, int n_in,
                              void* d_out, int out_size) {
    const float* x = (const float*)d_in[0];
    const float* W = (const float*)d_in[1];
    const float* A = (const float*)d_in[2];
    const float* B = (const float*)d_in[3];
    const int* idxp = (const int*)d_in[4];
    float* out = (float*)d_out;

    cudaFuncSetAttribute(k_gemm, cudaFuncAttributeMaxDynamicSharedMemorySize, SMEM_DYN);

    k_detect<<<1, 256>>>(idxp, MDIM);
    k_group<<<8, 256>>>(idxp);
    k_convx<<<dim3(MDIM / 16, KDIM / 256), 256>>>(x);
    k_convw<<<dim3(NDIM / 16, KDIM / 256), 256>>>(W);
    k_xa2<<<dim3(4, LNUM), 256>>>(x, A);
    k_gemm<<<dim3(MDIM / TILE_M, NDIM / TILE_N), 256, SMEM_DYN>>>(out);
    k_delta<<<dim3(NDIM / 128, LNUM), 128>>>(B, out);
}

// round 5
// speedup vs baseline: 1.3878x; 1.0335x over previous
#include <cuda_runtime.h>
#include <cuda_fp16.h>
#include <cstdint>

#define MDIM 2048
#define NDIM 11264
#define KDIM 2048
#define LNUM 16
#define RNK 16
#define HALF_N 5632

// GEMM tiling: CTA 128m x 128n, fp16 m16n8k16, BK=64, 3-buf pipeline, occ 2
#define TILE_M 128
#define TILE_N 128
#define NS (KDIM / 64)                   // 32 stages
#define STAGE_A (8 * 4 * 512)            // 16384 B  (8 m-tiles x 4 k-tiles)
#define STAGE_B (16 * 4 * 256)           // 16384 B  (16 n-tiles x 4 k-tiles)
#define STAGE_BYTES (STAGE_A + STAGE_B)  // 32768
#define NBUF 3
#define SMEM_DYN (NBUF * STAGE_BYTES)    // 98304

#define KT (KDIM / 16)                   // 128 k-tiles
#define XT_ROW (KT * 512)
#define WT_ROW (KT * 256)
#define WSCALE 256.0f
#define OSCALE 0.00390625f

// ---------------- device scratch ----------------
__device__ uint4 g_xt[(size_t)(MDIM / 16) * KT * 32];
__device__ uint2 g_wt[(size_t)(NDIM / 8) * KT * 32];
__device__ float g_xa[MDIM * 32];
__device__ int   g_cnt[LNUM];
__device__ int   g_list[LNUM * MDIM];
__device__ int   g_is64;

__device__ __forceinline__ int load_idx(const int* p, int t) {
    return g_is64 ? p[2 * t] : p[t];
}

// ---------------- helpers ----------------
__device__ __forceinline__ uint32_t smem_u32(const void* p) {
    uint32_t a;
    asm("{ .reg .u64 t; cvta.to.shared.u64 t, %1; cvt.u32.u64 %0, t; }" : "=r"(a) : "l"(p));
    return a;
}
__device__ __forceinline__ void cpasync16(uint32_t dst, const void* src) {
    asm volatile("cp.async.cg.shared.global [%0], [%1], 16;" :: "r"(dst), "l"(src));
}
__device__ __forceinline__ void cp_commit() {
    asm volatile("cp.async.commit_group;" ::: "memory");
}
template <int N> __device__ __forceinline__ void cp_wait() {
    asm volatile("cp.async.wait_group %0;" :: "n"(N) : "memory");
}
__device__ __forceinline__ uint32_t pack_h2(float lo, float hi) {
    __half2 h = __floats2half2_rn(lo, hi);
    return *(uint32_t*)&h;
}

// ---------------- 0) dtype detect + counter zero ----------------
__global__ void k_detect(const int* __restrict__ idxp, int n) {
    __shared__ int sbad;
    if (threadIdx.x == 0) sbad = 0;
    __syncthreads();
    int bad = 0;
    for (int i = threadIdx.x; i < n / 2; i += blockDim.x)
        if (idxp[2 * i + 1] != 0) bad = 1;
    if (bad) atomicExch(&sbad, 1);
    __syncthreads();
    if (threadIdx.x == 0) g_is64 = sbad ? 0 : 1;
    if (threadIdx.x < LNUM) g_cnt[threadIdx.x] = 0;
}

// ---------------- 1) group tokens by expert ----------------
__global__ void k_group(const int* __restrict__ idxp) {
    int t = blockIdx.x * blockDim.x + threadIdx.x;
    if (t < MDIM) {
        int l = load_idx(idxp, t);
        int pos = atomicAdd(&g_cnt[l], 1);
        g_list[l * MDIM + pos] = t;
    }
}

// ---------------- 2) convert x -> fragment-permuted fp16 ----------------
__global__ __launch_bounds__(256) void k_convx(const float* __restrict__ x) {
    __shared__ float s[16][260];
    const int tid = threadIdx.x;
    const int mt = blockIdx.x;
    const int m0 = mt * 16, k0 = blockIdx.y * 256;
#pragma unroll
    for (int p = 0; p < 4; p++) {
        int idx = tid + p * 256;
        int row = idx >> 6, c4 = (idx & 63) * 4;
        float4 v = *(const float4*)(x + (size_t)(m0 + row) * KDIM + k0 + c4);
        s[row][c4] = v.x; s[row][c4 + 1] = v.y; s[row][c4 + 2] = v.z; s[row][c4 + 3] = v.w;
    }
    __syncthreads();
    const int w = tid >> 5, lane = tid & 31;
    const int g = lane >> 2, tg2 = (lane & 3) * 2;
#pragma unroll
    for (int q = 0; q < 2; q++) {
        int ktl = w * 2 + q;
        int kc = ktl * 16;
        uint32_t a0 = pack_h2(s[g][kc + tg2], s[g][kc + tg2 + 1]);
        uint32_t a1 = pack_h2(s[g + 8][kc + tg2], s[g + 8][kc + tg2 + 1]);
        uint32_t a2 = pack_h2(s[g][kc + tg2 + 8], s[g][kc + tg2 + 9]);
        uint32_t a3 = pack_h2(s[g + 8][kc + tg2 + 8], s[g + 8][kc + tg2 + 9]);
        int ktg = blockIdx.y * 16 + ktl;
        g_xt[((size_t)mt * KT + ktg) * 32 + lane] = make_uint4(a0, a1, a2, a3);
    }
}

// ---------------- 3) convert W -> fragment-permuted fp16 (scaled x256) ------
__global__ __launch_bounds__(256) void k_convw(const float* __restrict__ W) {
    __shared__ float s[16][260];
    const int tid = threadIdx.x;
    const int n0 = blockIdx.x * 16, k0 = blockIdx.y * 256;
#pragma unroll
    for (int p = 0; p < 4; p++) {
        int idx = tid + p * 256;
        int row = idx >> 6, c4 = (idx & 63) * 4;
        float4 v = *(const float4*)(W + (size_t)(n0 + row) * KDIM + k0 + c4);
        s[row][c4] = v.x * WSCALE; s[row][c4 + 1] = v.y * WSCALE;
        s[row][c4 + 2] = v.z * WSCALE; s[row][c4 + 3] = v.w * WSCALE;
    }
    __syncthreads();
    const int w = tid >> 5, lane = tid & 31;
    const int g = lane >> 2, tg2 = (lane & 3) * 2;
#pragma unroll
    for (int q = 0; q < 2; q++) {
        int ktl = w * 2 + q;
        int kc = ktl * 16;
        int ktg = blockIdx.y * 16 + ktl;
#pragma unroll
        for (int nsub = 0; nsub < 2; nsub++) {
            uint32_t b0 = pack_h2(s[nsub * 8 + g][kc + tg2], s[nsub * 8 + g][kc + tg2 + 1]);
            uint32_t b1 = pack_h2(s[nsub * 8 + g][kc + tg2 + 8], s[nsub * 8 + g][kc + tg2 + 9]);
            int nt = blockIdx.x * 2 + nsub;
            g_wt[((size_t)nt * KT + ktg) * 32 + lane] = make_uint2(b0, b1);
        }
    }
}

// ---------------- 4) xa, expert-grouped ----------------
__global__ __launch_bounds__(256) void k_xa2(const float* __restrict__ x,
                                             const float* __restrict__ A) {
    __shared__ float As[128][33];
    __shared__ float xs[32][128];
    __shared__ int stok[32];
    const int l = blockIdx.y;
    const int cnt = g_cnt[l];
    const int tid = threadIdx.x, w = tid >> 5, lane = tid & 31;

    for (int ibase = blockIdx.x * 32; ibase < cnt; ibase += gridDim.x * 32) {
        if (tid < 32)
            stok[tid] = (ibase + tid < cnt) ? g_list[l * MDIM + ibase + tid] : -1;
        __syncthreads();
        float acc[4] = {0.f, 0.f, 0.f, 0.f};
        for (int ch = 0; ch < KDIM / 128; ch++) {
            const int d0 = ch * 128;
#pragma unroll
            for (int j = 0; j < 16; j++) {
                int idx = tid + j * 256;
                int dd = idx >> 5, c = idx & 31;
                As[dd][c] = A[((size_t)l * KDIM + d0 + dd) * 32 + c];
            }
#pragma unroll
            for (int j = 0; j < 16; j++) {
                int idx = tid + j * 256;
                int slot = idx >> 7, dd = idx & 127;
                int t = stok[slot];
                xs[slot][dd] = (t >= 0) ? x[(size_t)t * KDIM + d0 + dd] : 0.f;
            }
            __syncthreads();
            const float4* xv0 = (const float4*)xs[w * 4 + 0];
            const float4* xv1 = (const float4*)xs[w * 4 + 1];
            const float4* xv2 = (const float4*)xs[w * 4 + 2];
            const float4* xv3 = (const float4*)xs[w * 4 + 3];
#pragma unroll
            for (int q = 0; q < 32; q++) {
                float a0 = As[q * 4 + 0][lane];
                float a1 = As[q * 4 + 1][lane];
                float a2 = As[q * 4 + 2][lane];
                float a3 = As[q * 4 + 3][lane];
                float4 v0 = xv0[q], v1 = xv1[q], v2 = xv2[q], v3 = xv3[q];
                acc[0] += v0.x * a0 + v0.y * a1 + v0.z * a2 + v0.w * a3;
                acc[1] += v1.x * a0 + v1.y * a1 + v1.z * a2 + v1.w * a3;
                acc[2] += v2.x * a0 + v2.y * a1 + v2.z * a2 + v2.w * a3;
                acc[3] += v3.x * a0 + v3.y * a1 + v3.z * a2 + v3.w * a3;
            }
            __syncthreads();
        }
#pragma unroll
        for (int tk = 0; tk < 4; tk++) {
            int t = stok[w * 4 + tk];
            if (t >= 0) g_xa[t * 32 + lane] = acc[tk];
        }
        __syncthreads();
    }
}

// ---------------- 5) fp16 mma.sync GEMM, occ=2 ----------------
__global__ __launch_bounds__(256, 2) void k_gemm(float* __restrict__ out) {
    extern __shared__ char dyn[];
    const uint32_t dbase = smem_u32(dyn);

    const int tid = threadIdx.x;
    const int wid = tid >> 5;
    const int lane = tid & 31;
    const int mt0 = blockIdx.x * 8;    // 8 m-tiles of 16 rows
    const int nt0 = blockIdx.y * 16;   // 16 n-tiles of 8 cols
    const int mhalf = wid & 1;         // warp tile 64m x 32n
    const int nq = wid >> 1;           // 0..3

    const char* gA = (const char*)g_xt;
    const char* gB = (const char*)g_wt;

    auto issue_stage = [&](int s, int b) {
        const uint32_t abase = dbase + b * STAGE_BYTES;
        const uint32_t bbase = abase + STAGE_A;
#pragma unroll
        for (int j = 0; j < 4; j++) {
            int c = tid + j * 256;           // 1024 A chunks of 16B
            int mtl = c >> 7, r = c & 127;
            const char* src = gA + (size_t)(mt0 + mtl) * XT_ROW + s * 2048 + r * 16;
            cpasync16(abase + mtl * 2048 + r * 16, src);
        }
#pragma unroll
        for (int j = 0; j < 4; j++) {
            int c = tid + j * 256;           // 1024 B chunks of 16B
            int ntl = c >> 6, r = c & 63;
            const char* src = gB + (size_t)(nt0 + ntl) * WT_ROW + s * 1024 + r * 16;
            cpasync16(bbase + ntl * 1024 + r * 16, src);
        }
        cp_commit();
    };

    float c[4][4][4];
#pragma unroll
    for (int i = 0; i < 4; i++)
#pragma unroll
        for (int j = 0; j < 4; j++)
#pragma unroll
            for (int q = 0; q < 4; q++) c[i][j][q] = 0.f;

    issue_stage(0, 0);
    issue_stage(1, 1);

#pragma unroll 1
    for (int s = 0; s < NS; s++) {
        if (s < NS - 1) cp_wait<1>();
        else cp_wait<0>();
        __syncthreads();

        if (s + 2 < NS) issue_stage(s + 2, (s + 2) % 3);

        const char* sa = dyn + (s % 3) * STAGE_BYTES;
        const char* sb = sa + STAGE_A;

#pragma unroll
        for (int ktl = 0; ktl < 4; ktl++) {
            uint4 a[4];
            uint2 bfr[4];
#pragma unroll
            for (int i = 0; i < 4; i++) {
                int mtl = mhalf * 4 + i;
                a[i] = *(const uint4*)(sa + mtl * 2048 + ktl * 512 + lane * 16);
            }
#pragma unroll
            for (int j = 0; j < 4; j++) {
                int ntl = nq * 4 + j;
                bfr[j] = *(const uint2*)(sb + ntl * 1024 + ktl * 256 + lane * 8);
            }
#pragma unroll
            for (int i = 0; i < 4; i++)
#pragma unroll
                for (int j = 0; j < 4; j++) {
                    asm volatile(
                        "mma.sync.aligned.m16n8k16.row.col.f32.f16.f16.f32 "
                        "{%0,%1,%2,%3}, {%4,%5,%6,%7}, {%8,%9}, {%0,%1,%2,%3};\n"
                        : "+f"(c[i][j][0]), "+f"(c[i][j][1]),
                          "+f"(c[i][j][2]), "+f"(c[i][j][3])
                        : "r"(a[i].x), "r"(a[i].y), "r"(a[i].z), "r"(a[i].w),
                          "r"(bfr[j].x), "r"(bfr[j].y));
                }
        }
    }

    // epilogue (undo x256 W scaling)
    const int g = lane >> 2, tg = lane & 3;
    const int m0 = blockIdx.x * TILE_M, n0 = blockIdx.y * TILE_N;
#pragma unroll
    for (int i = 0; i < 4; i++) {
        int row0 = m0 + mhalf * 64 + i * 16 + g;
#pragma unroll
        for (int j = 0; j < 4; j++) {
            int col = n0 + nq * 32 + j * 8 + tg * 2;
            *(float2*)(out + (size_t)row0 * NDIM + col) =
                make_float2(c[i][j][0] * OSCALE, c[i][j][1] * OSCALE);
            *(float2*)(out + (size_t)(row0 + 8) * NDIM + col) =
                make_float2(c[i][j][2] * OSCALE, c[i][j][3] * OSCALE);
        }
    }
}

// ---------------- 6) rank-16 delta ----------------
__global__ __launch_bounds__(128) void k_delta(const float* __restrict__ B,
                                               float* __restrict__ out) {
    int l = blockIdx.y;
    int n0 = blockIdx.x * 128;
    int h = (n0 >= HALF_N) ? 16 : 0;

    __shared__ float Bs[RNK][128];
    for (int i = threadIdx.x; i < RNK * 128; i += 128) {
        int r = i >> 7, cc = i & 127;
        Bs[r][cc] = B[((size_t)l * RNK + r) * NDIM + n0 + cc];
    }
    __syncthreads();

    int cnt = g_cnt[l];
    int c = threadIdx.x;
#pragma unroll 2
    for (int i = 0; i < cnt; i++) {
        int t = g_list[l * MDIM + i];
        const float* xr = g_xa + t * 32 + h;
        float acc = 0.f;
#pragma unroll
        for (int r = 0; r < RNK; r++) acc += xr[r] * Bs[r][c];
        size_t o = (size_t)t * NDIM + n0 + c;
        out[o] += acc;
    }
}

// ---------------- launch (k_gemm moved to index 3 for ncu capture) ----------
extern "C" void kernel_launch(void* const* d_in, const int* in_sizes, int n_in,
                              void* d_out, int out_size) {
    const float* x = (const float*)d_in[0];
    const float* W = (const float*)d_in[1];
    const float* A = (const float*)d_in[2];
    const float* B = (const float*)d_in[3];
    const int* idxp = (const int*)d_in[4];
    float* out = (float*)d_out;

    cudaFuncSetAttribute(k_gemm, cudaFuncAttributeMaxDynamicSharedMemorySize, SMEM_DYN);

    k_detect<<<1, 256>>>(idxp, MDIM);
    k_convx<<<dim3(MDIM / 16, KDIM / 256), 256>>>(x);
    k_convw<<<dim3(NDIM / 16, KDIM / 256), 256>>>(W);
    k_gemm<<<dim3(MDIM / TILE_M, NDIM / TILE_N), 256, SMEM_DYN>>>(out);
    k_group<<<8, 256>>>(idxp);
    k_xa2<<<dim3(4, LNUM), 256>>>(x, A);
    k_delta<<<dim3(NDIM / 128, LNUM), 128>>>(B, out);
}

// round 8
// speedup vs baseline: 1.8533x; 1.3354x over previous
#include <cuda_runtime.h>
#include <cuda_fp16.h>
#include <cstdint>

#define MDIM 2048
#define NDIM 11264
#define KDIM 2048
#define LNUM 16
#define RNK 16
#define HALF_N 5632

// GEMM tiling: CTA 128m x 128n, fp16 m16n8k16, BK=64, 3-buf pipeline, occ 2
#define TILE_M 128
#define TILE_N 128
#define NS (KDIM / 64)                   // 32 stages
#define STAGE_A (8 * 4 * 512)            // 16384 B
#define STAGE_B (16 * 4 * 256)           // 16384 B
#define STAGE_BYTES (STAGE_A + STAGE_B)  // 32768
#define NBUF 3
#define SMEM_DYN (NBUF * STAGE_BYTES)    // 98304

#define KT (KDIM / 16)                   // 128 k-tiles
#define XT_ROW (KT * 512)
#define WT_ROW (KT * 256)
#define WSCALE 256.0f
#define OSCALE 0.00390625f

#define DN 512                           // delta: cols per block

// ---------------- device scratch ----------------
__device__ uint4 g_xt[(size_t)(MDIM / 16) * KT * 32];
__device__ uint2 g_wt[(size_t)(NDIM / 8) * KT * 32];
__device__ float g_xa[MDIM * 32];
__device__ int   g_cnt[LNUM];
__device__ int   g_list[LNUM * MDIM];
__device__ int   g_is64;

__device__ __forceinline__ int load_idx(const int* p, int t) {
    return g_is64 ? p[2 * t] : p[t];
}

// ---------------- helpers ----------------
__device__ __forceinline__ uint32_t smem_u32(const void* p) {
    uint32_t a;
    asm("{ .reg .u64 t; cvta.to.shared.u64 t, %1; cvt.u32.u64 %0, t; }" : "=r"(a) : "l"(p));
    return a;
}
__device__ __forceinline__ void cpasync16(uint32_t dst, const void* src) {
    asm volatile("cp.async.cg.shared.global [%0], [%1], 16;" :: "r"(dst), "l"(src));
}
__device__ __forceinline__ void cp_commit() {
    asm volatile("cp.async.commit_group;" ::: "memory");
}
template <int N> __device__ __forceinline__ void cp_wait() {
    asm volatile("cp.async.wait_group %0;" :: "n"(N) : "memory");
}
__device__ __forceinline__ uint32_t pack_h2(float lo, float hi) {
    __half2 h = __floats2half2_rn(lo, hi);
    return *(uint32_t*)&h;
}

// ---------------- 0) dtype detect + counter zero ----------------
__global__ void k_detect(const int* __restrict__ idxp, int n) {
    __shared__ int sbad;
    if (threadIdx.x == 0) sbad = 0;
    __syncthreads();
    int bad = 0;
    for (int i = threadIdx.x; i < n / 2; i += blockDim.x)
        if (idxp[2 * i + 1] != 0) bad = 1;
    if (bad) atomicExch(&sbad, 1);
    __syncthreads();
    if (threadIdx.x == 0) g_is64 = sbad ? 0 : 1;
    if (threadIdx.x < LNUM) g_cnt[threadIdx.x] = 0;
}

// ---------------- 1) group tokens by expert ----------------
__global__ void k_group(const int* __restrict__ idxp) {
    int t = blockIdx.x * blockDim.x + threadIdx.x;
    if (t < MDIM) {
        int l = load_idx(idxp, t);
        int pos = atomicAdd(&g_cnt[l], 1);
        g_list[l * MDIM + pos] = t;
    }
}

// ---------------- 2) convert x -> fragment-permuted fp16 ----------------
__global__ __launch_bounds__(256) void k_convx(const float* __restrict__ x) {
    __shared__ float s[16][260];
    const int tid = threadIdx.x;
    const int mt = blockIdx.x;
    const int m0 = mt * 16, k0 = blockIdx.y * 256;
#pragma unroll
    for (int p = 0; p < 4; p++) {
        int idx = tid + p * 256;
        int row = idx >> 6, c4 = (idx & 63) * 4;
        float4 v = *(const float4*)(x + (size_t)(m0 + row) * KDIM + k0 + c4);
        s[row][c4] = v.x; s[row][c4 + 1] = v.y; s[row][c4 + 2] = v.z; s[row][c4 + 3] = v.w;
    }
    __syncthreads();
    const int w = tid >> 5, lane = tid & 31;
    const int g = lane >> 2, tg2 = (lane & 3) * 2;
#pragma unroll
    for (int q = 0; q < 2; q++) {
        int ktl = w * 2 + q;
        int kc = ktl * 16;
        uint32_t a0 = pack_h2(s[g][kc + tg2], s[g][kc + tg2 + 1]);
        uint32_t a1 = pack_h2(s[g + 8][kc + tg2], s[g + 8][kc + tg2 + 1]);
        uint32_t a2 = pack_h2(s[g][kc + tg2 + 8], s[g][kc + tg2 + 9]);
        uint32_t a3 = pack_h2(s[g + 8][kc + tg2 + 8], s[g + 8][kc + tg2 + 9]);
        int ktg = blockIdx.y * 16 + ktl;
        g_xt[((size_t)mt * KT + ktg) * 32 + lane] = make_uint4(a0, a1, a2, a3);
    }
}

// ---------------- 3) convert W -> fragment-permuted fp16 (scaled x256) ------
__global__ __launch_bounds__(256) void k_convw(const float* __restrict__ W) {
    __shared__ float s[16][260];
    const int tid = threadIdx.x;
    const int n0 = blockIdx.x * 16, k0 = blockIdx.y * 256;
#pragma unroll
    for (int p = 0; p < 4; p++) {
        int idx = tid + p * 256;
        int row = idx >> 6, c4 = (idx & 63) * 4;
        float4 v = *(const float4*)(W + (size_t)(n0 + row) * KDIM + k0 + c4);
        s[row][c4] = v.x * WSCALE; s[row][c4 + 1] = v.y * WSCALE;
        s[row][c4 + 2] = v.z * WSCALE; s[row][c4 + 3] = v.w * WSCALE;
    }
    __syncthreads();
    const int w = tid >> 5, lane = tid & 31;
    const int g = lane >> 2, tg2 = (lane & 3) * 2;
#pragma unroll
    for (int q = 0; q < 2; q++) {
        int ktl = w * 2 + q;
        int kc = ktl * 16;
        int ktg = blockIdx.y * 16 + ktl;
#pragma unroll
        for (int nsub = 0; nsub < 2; nsub++) {
            uint32_t b0 = pack_h2(s[nsub * 8 + g][kc + tg2], s[nsub * 8 + g][kc + tg2 + 1]);
            uint32_t b1 = pack_h2(s[nsub * 8 + g][kc + tg2 + 8], s[nsub * 8 + g][kc + tg2 + 9]);
            int nt = blockIdx.x * 2 + nsub;
            g_wt[((size_t)nt * KT + ktg) * 32 + lane] = make_uint2(b0, b1);
        }
    }
}

// ---------------- 4) xa, expert-grouped ----------------
__global__ __launch_bounds__(256) void k_xa2(const float* __restrict__ x,
                                             const float* __restrict__ A) {
    __shared__ float As[128][33];
    __shared__ float xs[32][128];
    __shared__ int stok[32];
    const int l = blockIdx.y;
    const int cnt = g_cnt[l];
    const int tid = threadIdx.x, w = tid >> 5, lane = tid & 31;

    for (int ibase = blockIdx.x * 32; ibase < cnt; ibase += gridDim.x * 32) {
        if (tid < 32)
            stok[tid] = (ibase + tid < cnt) ? g_list[l * MDIM + ibase + tid] : -1;
        __syncthreads();
        float acc[4] = {0.f, 0.f, 0.f, 0.f};
        for (int ch = 0; ch < KDIM / 128; ch++) {
            const int d0 = ch * 128;
#pragma unroll
            for (int j = 0; j < 16; j++) {
                int idx = tid + j * 256;
                int dd = idx >> 5, c = idx & 31;
                As[dd][c] = A[((size_t)l * KDIM + d0 + dd) * 32 + c];
            }
#pragma unroll
            for (int j = 0; j < 16; j++) {
                int idx = tid + j * 256;
                int slot = idx >> 7, dd = idx & 127;
                int t = stok[slot];
                xs[slot][dd] = (t >= 0) ? x[(size_t)t * KDIM + d0 + dd] : 0.f;
            }
            __syncthreads();
            const float4* xv0 = (const float4*)xs[w * 4 + 0];
            const float4* xv1 = (const float4*)xs[w * 4 + 1];
            const float4* xv2 = (const float4*)xs[w * 4 + 2];
            const float4* xv3 = (const float4*)xs[w * 4 + 3];
#pragma unroll
            for (int q = 0; q < 32; q++) {
                float a0 = As[q * 4 + 0][lane];
                float a1 = As[q * 4 + 1][lane];
                float a2 = As[q * 4 + 2][lane];
                float a3 = As[q * 4 + 3][lane];
                float4 v0 = xv0[q], v1 = xv1[q], v2 = xv2[q], v3 = xv3[q];
                acc[0] += v0.x * a0 + v0.y * a1 + v0.z * a2 + v0.w * a3;
                acc[1] += v1.x * a0 + v1.y * a1 + v1.z * a2 + v1.w * a3;
                acc[2] += v2.x * a0 + v2.y * a1 + v2.z * a2 + v2.w * a3;
                acc[3] += v3.x * a0 + v3.y * a1 + v3.z * a2 + v3.w * a3;
            }
            __syncthreads();
        }
#pragma unroll
        for (int tk = 0; tk < 4; tk++) {
            int t = stok[w * 4 + tk];
            if (t >= 0) g_xa[t * 32 + lane] = acc[tk];
        }
        __syncthreads();
    }
}

// ---------------- 5) fp16 mma.sync GEMM, occ=2 ----------------
__global__ __launch_bounds__(256, 2) void k_gemm(float* __restrict__ out) {
    extern __shared__ char dyn[];
    const uint32_t dbase = smem_u32(dyn);

    const int tid = threadIdx.x;
    const int wid = tid >> 5;
    const int lane = tid & 31;
    const int mt0 = blockIdx.x * 8;
    const int nt0 = blockIdx.y * 16;
    const int mhalf = wid & 1;
    const int nq = wid >> 1;

    const char* gA = (const char*)g_xt;
    const char* gB = (const char*)g_wt;

    auto issue_stage = [&](int s, int b) {
        const uint32_t abase = dbase + b * STAGE_BYTES;
        const uint32_t bbase = abase + STAGE_A;
#pragma unroll
        for (int j = 0; j < 4; j++) {
            int c = tid + j * 256;
            int mtl = c >> 7, r = c & 127;
            const char* src = gA + (size_t)(mt0 + mtl) * XT_ROW + s * 2048 + r * 16;
            cpasync16(abase + mtl * 2048 + r * 16, src);
        }
#pragma unroll
        for (int j = 0; j < 4; j++) {
            int c = tid + j * 256;
            int ntl = c >> 6, r = c & 63;
            const char* src = gB + (size_t)(nt0 + ntl) * WT_ROW + s * 1024 + r * 16;
            cpasync16(bbase + ntl * 1024 + r * 16, src);
        }
        cp_commit();
    };

    float c[4][4][4];
#pragma unroll
    for (int i = 0; i < 4; i++)
#pragma unroll
        for (int j = 0; j < 4; j++)
#pragma unroll
            for (int q = 0; q < 4; q++) c[i][j][q] = 0.f;

    issue_stage(0, 0);
    issue_stage(1, 1);

#pragma unroll 1
    for (int s = 0; s < NS; s++) {
        if (s < NS - 1) cp_wait<1>();
        else cp_wait<0>();
        __syncthreads();

        if (s + 2 < NS) issue_stage(s + 2, (s + 2) % 3);

        const char* sa = dyn + (s % 3) * STAGE_BYTES;
        const char* sb = sa + STAGE_A;

#pragma unroll
        for (int ktl = 0; ktl < 4; ktl++) {
            uint4 a[4];
            uint2 bfr[4];
#pragma unroll
            for (int i = 0; i < 4; i++) {
                int mtl = mhalf * 4 + i;
                a[i] = *(const uint4*)(sa + mtl * 2048 + ktl * 512 + lane * 16);
            }
#pragma unroll
            for (int j = 0; j < 4; j++) {
                int ntl = nq * 4 + j;
                bfr[j] = *(const uint2*)(sb + ntl * 1024 + ktl * 256 + lane * 8);
            }
#pragma unroll
            for (int i = 0; i < 4; i++)
#pragma unroll
                for (int j = 0; j < 4; j++) {
                    asm volatile(
                        "mma.sync.aligned.m16n8k16.row.col.f32.f16.f16.f32 "
                        "{%0,%1,%2,%3}, {%4,%5,%6,%7}, {%8,%9}, {%0,%1,%2,%3};\n"
                        : "+f"(c[i][j][0]), "+f"(c[i][j][1]),
                          "+f"(c[i][j][2]), "+f"(c[i][j][3])
                        : "r"(a[i].x), "r"(a[i].y), "r"(a[i].z), "r"(a[i].w),
                          "r"(bfr[j].x), "r"(bfr[j].y));
                }
        }
    }

    const int g = lane >> 2, tg = lane & 3;
    const int m0 = blockIdx.x * TILE_M, n0 = blockIdx.y * TILE_N;
#pragma unroll
    for (int i = 0; i < 4; i++) {
        int row0 = m0 + mhalf * 64 + i * 16 + g;
#pragma unroll
        for (int j = 0; j < 4; j++) {
            int col = n0 + nq * 32 + j * 8 + tg * 2;
            *(float2*)(out + (size_t)row0 * NDIM + col) =
                make_float2(c[i][j][0] * OSCALE, c[i][j][1] * OSCALE);
            *(float2*)(out + (size_t)(row0 + 8) * NDIM + col) =
                make_float2(c[i][j][2] * OSCALE, c[i][j][3] * OSCALE);
        }
    }
}

// ---------------- 6) rank-16 delta: smem-staged, 4 tokens in flight ---------
__global__ __launch_bounds__(128) void k_delta(const float* __restrict__ B,
                                               float* __restrict__ out) {
    const int l = blockIdx.y;
    const int n0 = blockIdx.x * DN;
    const int h = (n0 >= HALF_N) ? 16 : 0;
    const int tid = threadIdx.x;

    __shared__ float4 Bs[RNK][DN / 4];   // 32 KB
    __shared__ float  xas[128][17];      // padded
    __shared__ int    stok[128];

    // stage B slice for this (expert, n-chunk)
    for (int i = tid; i < RNK * (DN / 4); i += 128) {
        int r = i >> 7, cc = i & 127;
        Bs[r][cc] = *(const float4*)(B + ((size_t)l * RNK + r) * NDIM + n0 + cc * 4);
    }
    const int cnt = g_cnt[l];

    for (int ib = 0; ib < cnt; ib += 128) {
        const int bc = min(128, cnt - ib);
        __syncthreads();   // Bs ready (first iter) / prev batch done (later)
        if (tid < bc) stok[tid] = g_list[l * MDIM + ib + tid];
        __syncthreads();
        // stage xa rows for this batch: bc x 16 floats
        for (int i = tid; i < bc * 16; i += 128) {
            int s = i >> 4, r = i & 15;
            xas[s][r] = g_xa[stok[s] * 32 + h + r];
        }
        __syncthreads();

#pragma unroll 1
        for (int i0 = 0; i0 < bc; i0 += 4) {
            float4 acc0 = make_float4(0.f, 0.f, 0.f, 0.f);
            float4 acc1 = acc0, acc2 = acc0, acc3 = acc0;
#pragma unroll
            for (int r = 0; r < RNK; r++) {
                float4 b4 = Bs[r][tid];
                float s0 = xas[i0 + 0][r];
                float s1 = xas[(i0 + 1) & 127][r];
                float s2 = xas[(i0 + 2) & 127][r];
                float s3 = xas[(i0 + 3) & 127][r];
                acc0.x += s0 * b4.x; acc0.y += s0 * b4.y; acc0.z += s0 * b4.z; acc0.w += s0 * b4.w;
                acc1.x += s1 * b4.x; acc1.y += s1 * b4.y; acc1.z += s1 * b4.z; acc1.w += s1 * b4.w;
                acc2.x += s2 * b4.x; acc2.y += s2 * b4.y; acc2.z += s2 * b4.z; acc2.w += s2 * b4.w;
                acc3.x += s3 * b4.x; acc3.y += s3 * b4.y; acc3.z += s3 * b4.z; acc3.w += s3 * b4.w;
            }
            float4 accs[4] = {acc0, acc1, acc2, acc3};
#pragma unroll
            for (int tk = 0; tk < 4; tk++) {
                int ii = i0 + tk;
                if (ii < bc) {
                    float4* op = (float4*)(out + (size_t)stok[ii] * NDIM + n0 + tid * 4);
                    float4 v = *op;
                    v.x += accs[tk].x; v.y += accs[tk].y;
                    v.z += accs[tk].z; v.w += accs[tk].w;
                    *op = v;
                }
            }
        }
    }
}

// ---------------- launch (k_xa2 at capture index 3) ----------------
extern "C" void kernel_launch(void* const* d_in, const int* in_sizes, int n_in,
                              void* d_out, int out_size) {
    const float* x = (const float*)d_in[0];
    const float* W = (const float*)d_in[1];
    const float* A = (const float*)d_in[2];
    const float* B = (const float*)d_in[3];
    const int* idxp = (const int*)d_in[4];
    float* out = (float*)d_out;

    cudaFuncSetAttribute(k_gemm, cudaFuncAttributeMaxDynamicSharedMemorySize, SMEM_DYN);

    k_detect<<<1, 256>>>(idxp, MDIM);
    k_group<<<8, 256>>>(idxp);
    k_convx<<<dim3(MDIM / 16, KDIM / 256), 256>>>(x);
    k_xa2<<<dim3(4, LNUM), 256>>>(x, A);
    k_convw<<<dim3(NDIM / 16, KDIM / 256), 256>>>(W);
    k_gemm<<<dim3(MDIM / TILE_M, NDIM / TILE_N), 256, SMEM_DYN>>>(out);
    k_delta<<<dim3(NDIM / DN, LNUM), 128>>>(B, out);
}

// round 9
// speedup vs baseline: 2.3174x; 1.2504x over previous
#include <cuda_runtime.h>
#include <cuda_fp16.h>
#include <cstdint>

#define MDIM 2048
#define NDIM 11264
#define KDIM 2048
#define LNUM 16
#define RNK 16
#define HALF_N 5632

// GEMM tiling: CTA 128m x 128n, fp16 m16n8k16, BK=64, 3-buf pipeline, occ 2
#define TILE_M 128
#define TILE_N 128
#define NS (KDIM / 64)                   // 32 stages
#define STAGE_A (8 * 4 * 512)            // 16384 B
#define STAGE_B (16 * 4 * 256)           // 16384 B
#define STAGE_BYTES (STAGE_A + STAGE_B)  // 32768
#define NBUF 3
#define SMEM_DYN (NBUF * STAGE_BYTES)    // 98304

#define KT (KDIM / 16)                   // 128 k-tiles
#define XT_ROW (KT * 512)
#define WT_ROW (KT * 256)
#define WSCALE 256.0f
#define OSCALE 0.00390625f

#define DN 512                           // delta: cols per block
#define XKC 256                          // xa: k-chunk size

// ---------------- device scratch ----------------
__device__ uint4 g_xt[(size_t)(MDIM / 16) * KT * 32];
__device__ uint2 g_wt[(size_t)(NDIM / 8) * KT * 32];
__device__ float g_xa[MDIM * 32];
__device__ int   g_cnt[LNUM];
__device__ int   g_list[LNUM * MDIM];
__device__ int   g_is64;

__device__ __forceinline__ int load_idx(const int* p, int t) {
    return g_is64 ? p[2 * t] : p[t];
}

// ---------------- helpers ----------------
__device__ __forceinline__ uint32_t smem_u32(const void* p) {
    uint32_t a;
    asm("{ .reg .u64 t; cvta.to.shared.u64 t, %1; cvt.u32.u64 %0, t; }" : "=r"(a) : "l"(p));
    return a;
}
__device__ __forceinline__ void cpasync16(uint32_t dst, const void* src) {
    asm volatile("cp.async.cg.shared.global [%0], [%1], 16;" :: "r"(dst), "l"(src));
}
__device__ __forceinline__ void cp_commit() {
    asm volatile("cp.async.commit_group;" ::: "memory");
}
template <int N> __device__ __forceinline__ void cp_wait() {
    asm volatile("cp.async.wait_group %0;" :: "n"(N) : "memory");
}
__device__ __forceinline__ uint32_t pack_h2(float lo, float hi) {
    __half2 h = __floats2half2_rn(lo, hi);
    return *(uint32_t*)&h;
}

// ---------------- 0) dtype detect + counter zero ----------------
__global__ void k_detect(const int* __restrict__ idxp, int n) {
    __shared__ int sbad;
    if (threadIdx.x == 0) sbad = 0;
    __syncthreads();
    int bad = 0;
    for (int i = threadIdx.x; i < n / 2; i += blockDim.x)
        if (idxp[2 * i + 1] != 0) bad = 1;
    if (bad) atomicExch(&sbad, 1);
    __syncthreads();
    if (threadIdx.x == 0) g_is64 = sbad ? 0 : 1;
    if (threadIdx.x < LNUM) g_cnt[threadIdx.x] = 0;
}

// ---------------- 1) group tokens by expert + zero g_xa ----------------
__global__ void k_group(const int* __restrict__ idxp) {
    int t = blockIdx.x * blockDim.x + threadIdx.x;
    if (t < MDIM) {
        // zero xa accumulator (this launch's split-K partials atomically add)
        float4* z = (float4*)(g_xa + t * 32);
#pragma unroll
        for (int q = 0; q < 8; q++) z[q] = make_float4(0.f, 0.f, 0.f, 0.f);
        int l = load_idx(idxp, t);
        int pos = atomicAdd(&g_cnt[l], 1);
        g_list[l * MDIM + pos] = t;
    }
}

// ---------------- 2) convert x -> fragment-permuted fp16 ----------------
__global__ __launch_bounds__(256) void k_convx(const float* __restrict__ x) {
    __shared__ float s[16][260];
    const int tid = threadIdx.x;
    const int mt = blockIdx.x;
    const int m0 = mt * 16, k0 = blockIdx.y * 256;
#pragma unroll
    for (int p = 0; p < 4; p++) {
        int idx = tid + p * 256;
        int row = idx >> 6, c4 = (idx & 63) * 4;
        float4 v = *(const float4*)(x + (size_t)(m0 + row) * KDIM + k0 + c4);
        s[row][c4] = v.x; s[row][c4 + 1] = v.y; s[row][c4 + 2] = v.z; s[row][c4 + 3] = v.w;
    }
    __syncthreads();
    const int w = tid >> 5, lane = tid & 31;
    const int g = lane >> 2, tg2 = (lane & 3) * 2;
#pragma unroll
    for (int q = 0; q < 2; q++) {
        int ktl = w * 2 + q;
        int kc = ktl * 16;
        uint32_t a0 = pack_h2(s[g][kc + tg2], s[g][kc + tg2 + 1]);
        uint32_t a1 = pack_h2(s[g + 8][kc + tg2], s[g + 8][kc + tg2 + 1]);
        uint32_t a2 = pack_h2(s[g][kc + tg2 + 8], s[g][kc + tg2 + 9]);
        uint32_t a3 = pack_h2(s[g + 8][kc + tg2 + 8], s[g + 8][kc + tg2 + 9]);
        int ktg = blockIdx.y * 16 + ktl;
        g_xt[((size_t)mt * KT + ktg) * 32 + lane] = make_uint4(a0, a1, a2, a3);
    }
}

// ---------------- 3) convert W -> fragment-permuted fp16 (scaled x256) ------
__global__ __launch_bounds__(256) void k_convw(const float* __restrict__ W) {
    __shared__ float s[16][260];
    const int tid = threadIdx.x;
    const int n0 = blockIdx.x * 16, k0 = blockIdx.y * 256;
#pragma unroll
    for (int p = 0; p < 4; p++) {
        int idx = tid + p * 256;
        int row = idx >> 6, c4 = (idx & 63) * 4;
        float4 v = *(const float4*)(W + (size_t)(n0 + row) * KDIM + k0 + c4);
        s[row][c4] = v.x * WSCALE; s[row][c4 + 1] = v.y * WSCALE;
        s[row][c4 + 2] = v.z * WSCALE; s[row][c4 + 3] = v.w * WSCALE;
    }
    __syncthreads();
    const int w = tid >> 5, lane = tid & 31;
    const int g = lane >> 2, tg2 = (lane & 3) * 2;
#pragma unroll
    for (int q = 0; q < 2; q++) {
        int ktl = w * 2 + q;
        int kc = ktl * 16;
        int ktg = blockIdx.y * 16 + ktl;
#pragma unroll
        for (int nsub = 0; nsub < 2; nsub++) {
            uint32_t b0 = pack_h2(s[nsub * 8 + g][kc + tg2], s[nsub * 8 + g][kc + tg2 + 1]);
            uint32_t b1 = pack_h2(s[nsub * 8 + g][kc + tg2 + 8], s[nsub * 8 + g][kc + tg2 + 9]);
            int nt = blockIdx.x * 2 + nsub;
            g_wt[((size_t)nt * KT + ktg) * 32 + lane] = make_uint2(b0, b1);
        }
    }
}

// ---------------- 4) xa: split-K, barrier-free token loop ----------------
// grid (k-chunk 0..7, expert 0..15). A chunk in smem once; each warp streams
// tokens independently; partial results accumulate into g_xa via red.global.
__global__ __launch_bounds__(256) void k_xa3(const float* __restrict__ x,
                                             const float* __restrict__ A) {
    __shared__ float As[XKC][33];
    const int l = blockIdx.y;
    const int d0 = blockIdx.x * XKC;
    const int tid = threadIdx.x, w = tid >> 5, lane = tid & 31;

    // stage A[l, d0:d0+256, 0:32]
#pragma unroll
    for (int j = 0; j < 32; j++) {
        int idx = tid + j * 256;
        int dd = idx >> 5, c = idx & 31;
        As[dd][c] = A[((size_t)l * KDIM + d0 + dd) * 32 + c];
    }
    __syncthreads();

    const int cnt = g_cnt[l];
#pragma unroll 1
    for (int i = w; i < cnt; i += 8) {
        const int t = g_list[l * MDIM + i];
        const float4* xr = (const float4*)(x + (size_t)t * KDIM + d0);
        float4 v0 = xr[lane * 2], v1 = xr[lane * 2 + 1];
        float xv[8] = {v0.x, v0.y, v0.z, v0.w, v1.x, v1.y, v1.z, v1.w};
        float acc = 0.f;
#pragma unroll
        for (int sl = 0; sl < 32; sl++) {
            float b0 = __shfl_sync(0xffffffffu, xv[0], sl);
            float b1 = __shfl_sync(0xffffffffu, xv[1], sl);
            float b2 = __shfl_sync(0xffffffffu, xv[2], sl);
            float b3 = __shfl_sync(0xffffffffu, xv[3], sl);
            float b4 = __shfl_sync(0xffffffffu, xv[4], sl);
            float b5 = __shfl_sync(0xffffffffu, xv[5], sl);
            float b6 = __shfl_sync(0xffffffffu, xv[6], sl);
            float b7 = __shfl_sync(0xffffffffu, xv[7], sl);
            acc += b0 * As[sl * 8 + 0][lane] + b1 * As[sl * 8 + 1][lane] +
                   b2 * As[sl * 8 + 2][lane] + b3 * As[sl * 8 + 3][lane] +
                   b4 * As[sl * 8 + 4][lane] + b5 * As[sl * 8 + 5][lane] +
                   b6 * As[sl * 8 + 6][lane] + b7 * As[sl * 8 + 7][lane];
        }
        atomicAdd(&g_xa[t * 32 + lane], acc);
    }
}

// ---------------- 5) fp16 mma.sync GEMM, occ=2 ----------------
__global__ __launch_bounds__(256, 2) void k_gemm(float* __restrict__ out) {
    extern __shared__ char dyn[];
    const uint32_t dbase = smem_u32(dyn);

    const int tid = threadIdx.x;
    const int wid = tid >> 5;
    const int lane = tid & 31;
    const int mt0 = blockIdx.x * 8;
    const int nt0 = blockIdx.y * 16;
    const int mhalf = wid & 1;
    const int nq = wid >> 1;

    const char* gA = (const char*)g_xt;
    const char* gB = (const char*)g_wt;

    auto issue_stage = [&](int s, int b) {
        const uint32_t abase = dbase + b * STAGE_BYTES;
        const uint32_t bbase = abase + STAGE_A;
#pragma unroll
        for (int j = 0; j < 4; j++) {
            int c = tid + j * 256;
            int mtl = c >> 7, r = c & 127;
            const char* src = gA + (size_t)(mt0 + mtl) * XT_ROW + s * 2048 + r * 16;
            cpasync16(abase + mtl * 2048 + r * 16, src);
        }
#pragma unroll
        for (int j = 0; j < 4; j++) {
            int c = tid + j * 256;
            int ntl = c >> 6, r = c & 63;
            const char* src = gB + (size_t)(nt0 + ntl) * WT_ROW + s * 1024 + r * 16;
            cpasync16(bbase + ntl * 1024 + r * 16, src);
        }
        cp_commit();
    };

    float c[4][4][4];
#pragma unroll
    for (int i = 0; i < 4; i++)
#pragma unroll
        for (int j = 0; j < 4; j++)
#pragma unroll
            for (int q = 0; q < 4; q++) c[i][j][q] = 0.f;

    issue_stage(0, 0);
    issue_stage(1, 1);

#pragma unroll 1
    for (int s = 0; s < NS; s++) {
        if (s < NS - 1) cp_wait<1>();
        else cp_wait<0>();
        __syncthreads();

        if (s + 2 < NS) issue_stage(s + 2, (s + 2) % 3);

        const char* sa = dyn + (s % 3) * STAGE_BYTES;
        const char* sb = sa + STAGE_A;

#pragma unroll
        for (int ktl = 0; ktl < 4; ktl++) {
            uint4 a[4];
            uint2 bfr[4];
#pragma unroll
            for (int i = 0; i < 4; i++) {
                int mtl = mhalf * 4 + i;
                a[i] = *(const uint4*)(sa + mtl * 2048 + ktl * 512 + lane * 16);
            }
#pragma unroll
            for (int j = 0; j < 4; j++) {
                int ntl = nq * 4 + j;
                bfr[j] = *(const uint2*)(sb + ntl * 1024 + ktl * 256 + lane * 8);
            }
#pragma unroll
            for (int i = 0; i < 4; i++)
#pragma unroll
                for (int j = 0; j < 4; j++) {
                    asm volatile(
                        "mma.sync.aligned.m16n8k16.row.col.f32.f16.f16.f32 "
                        "{%0,%1,%2,%3}, {%4,%5,%6,%7}, {%8,%9}, {%0,%1,%2,%3};\n"
                        : "+f"(c[i][j][0]), "+f"(c[i][j][1]),
                          "+f"(c[i][j][2]), "+f"(c[i][j][3])
                        : "r"(a[i].x), "r"(a[i].y), "r"(a[i].z), "r"(a[i].w),
                          "r"(bfr[j].x), "r"(bfr[j].y));
                }
        }
    }

    const int g = lane >> 2, tg = lane & 3;
    const int m0 = blockIdx.x * TILE_M, n0 = blockIdx.y * TILE_N;
#pragma unroll
    for (int i = 0; i < 4; i++) {
        int row0 = m0 + mhalf * 64 + i * 16 + g;
#pragma unroll
        for (int j = 0; j < 4; j++) {
            int col = n0 + nq * 32 + j * 8 + tg * 2;
            *(float2*)(out + (size_t)row0 * NDIM + col) =
                make_float2(c[i][j][0] * OSCALE, c[i][j][1] * OSCALE);
            *(float2*)(out + (size_t)(row0 + 8) * NDIM + col) =
                make_float2(c[i][j][2] * OSCALE, c[i][j][3] * OSCALE);
        }
    }
}

// ---------------- 6) rank-16 delta: smem-staged, 4 tokens in flight ---------
__global__ __launch_bounds__(128) void k_delta(const float* __restrict__ B,
                                               float* __restrict__ out) {
    const int l = blockIdx.y;
    const int n0 = blockIdx.x * DN;
    const int h = (n0 >= HALF_N) ? 16 : 0;
    const int tid = threadIdx.x;

    __shared__ float4 Bs[RNK][DN / 4];
    __shared__ float  xas[128][17];
    __shared__ int    stok[128];

    for (int i = tid; i < RNK * (DN / 4); i += 128) {
        int r = i >> 7, cc = i & 127;
        Bs[r][cc] = *(const float4*)(B + ((size_t)l * RNK + r) * NDIM + n0 + cc * 4);
    }
    const int cnt = g_cnt[l];

    for (int ib = 0; ib < cnt; ib += 128) {
        const int bc = min(128, cnt - ib);
        __syncthreads();
        if (tid < bc) stok[tid] = g_list[l * MDIM + ib + tid];
        __syncthreads();
        for (int i = tid; i < bc * 16; i += 128) {
            int s = i >> 4, r = i & 15;
            xas[s][r] = g_xa[stok[s] * 32 + h + r];
        }
        __syncthreads();

#pragma unroll 1
        for (int i0 = 0; i0 < bc; i0 += 4) {
            float4 acc0 = make_float4(0.f, 0.f, 0.f, 0.f);
            float4 acc1 = acc0, acc2 = acc0, acc3 = acc0;
#pragma unroll
            for (int r = 0; r < RNK; r++) {
                float4 b4 = Bs[r][tid];
                float s0 = xas[i0 + 0][r];
                float s1 = xas[(i0 + 1) & 127][r];
                float s2 = xas[(i0 + 2) & 127][r];
                float s3 = xas[(i0 + 3) & 127][r];
                acc0.x += s0 * b4.x; acc0.y += s0 * b4.y; acc0.z += s0 * b4.z; acc0.w += s0 * b4.w;
                acc1.x += s1 * b4.x; acc1.y += s1 * b4.y; acc1.z += s1 * b4.z; acc1.w += s1 * b4.w;
                acc2.x += s2 * b4.x; acc2.y += s2 * b4.y; acc2.z += s2 * b4.z; acc2.w += s2 * b4.w;
                acc3.x += s3 * b4.x; acc3.y += s3 * b4.y; acc3.z += s3 * b4.z; acc3.w += s3 * b4.w;
            }
            float4 accs[4] = {acc0, acc1, acc2, acc3};
#pragma unroll
            for (int tk = 0; tk < 4; tk++) {
                int ii = i0 + tk;
                if (ii < bc) {
                    float4* op = (float4*)(out + (size_t)stok[ii] * NDIM + n0 + tid * 4);
                    float4 v = *op;
                    v.x += accs[tk].x; v.y += accs[tk].y;
                    v.z += accs[tk].z; v.w += accs[tk].w;
                    *op = v;
                }
            }
        }
    }
}

// ---------------- launch (k_xa3 at capture index 3) ----------------
extern "C" void kernel_launch(void* const* d_in, const int* in_sizes, int n_in,
                              void* d_out, int out_size) {
    const float* x = (const float*)d_in[0];
    const float* W = (const float*)d_in[1];
    const float* A = (const float*)d_in[2];
    const float* B = (const float*)d_in[3];
    const int* idxp = (const int*)d_in[4];
    float* out = (float*)d_out;

    cudaFuncSetAttribute(k_gemm, cudaFuncAttributeMaxDynamicSharedMemorySize, SMEM_DYN);

    k_detect<<<1, 256>>>(idxp, MDIM);
    k_group<<<8, 256>>>(idxp);
    k_convx<<<dim3(MDIM / 16, KDIM / 256), 256>>>(x);
    k_xa3<<<dim3(KDIM / XKC, LNUM), 256>>>(x, A);
    k_convw<<<dim3(NDIM / 16, KDIM / 256), 256>>>(W);
    k_gemm<<<dim3(MDIM / TILE_M, NDIM / TILE_N), 256, SMEM_DYN>>>(out);
    k_delta<<<dim3(NDIM / DN, LNUM), 128>>>(B, out);
}

// round 13
// speedup vs baseline: 2.4879x; 1.0736x over previous
#include <cuda_runtime.h>
#include <cuda_fp16.h>
#include <cstdint>

#define MDIM 2048
#define NDIM 11264
#define KDIM 2048
#define LNUM 16
#define RNK 16
#define HALF_N 5632

// GEMM tiling: CTA 128m x 128n, fp16 m16n8k16, BK=64, 3-buf pipeline, occ 2
#define TILE_M 128
#define TILE_N 128
#define NS (KDIM / 64)                   // 32 stages
#define STAGE_A (8 * 4 * 512)            // 16384 B
#define STAGE_B (16 * 4 * 256)           // 16384 B
#define STAGE_BYTES (STAGE_A + STAGE_B)  // 32768
#define NBUF 3
#define SMEM_DYN (NBUF * STAGE_BYTES)    // 98304

#define KT (KDIM / 16)                   // 128 k-tiles
#define XT_ROW (KT * 512)
#define WT_ROW (KT * 256)
#define WSCALE 256.0f
#define OSCALE 0.00390625f

#define DN 512                           // delta: cols per block
#define XKC 128                          // xa: k-chunk size (16 chunks)

// ---------------- device scratch ----------------
__device__ uint4 g_xt[(size_t)(MDIM / 16) * KT * 32];
__device__ uint2 g_wt[(size_t)(NDIM / 8) * KT * 32];
__device__ float g_xa[MDIM * 32];
__device__ int   g_cnt[LNUM];
__device__ int   g_list[LNUM * MDIM];
__device__ int   g_is64;

__device__ __forceinline__ int load_idx(const int* p, int t) {
    return g_is64 ? p[2 * t] : p[t];
}

// ---------------- helpers ----------------
__device__ __forceinline__ uint32_t smem_u32(const void* p) {
    uint32_t a;
    asm("{ .reg .u64 t; cvta.to.shared.u64 t, %1; cvt.u32.u64 %0, t; }" : "=r"(a) : "l"(p));
    return a;
}
__device__ __forceinline__ void cpasync16(uint32_t dst, const void* src) {
    asm volatile("cp.async.cg.shared.global [%0], [%1], 16;" :: "r"(dst), "l"(src));
}
__device__ __forceinline__ void cp_commit() {
    asm volatile("cp.async.commit_group;" ::: "memory");
}
template <int N> __device__ __forceinline__ void cp_wait() {
    asm volatile("cp.async.wait_group %0;" :: "n"(N) : "memory");
}
__device__ __forceinline__ uint32_t pack_h2(float lo, float hi) {
    __half2 h = __floats2half2_rn(lo, hi);
    return *(uint32_t*)&h;
}

// ---------------- 0) dtype detect + counter zero ----------------
__global__ void k_detect(const int* __restrict__ idxp, int n) {
    __shared__ int sbad;
    if (threadIdx.x == 0) sbad = 0;
    __syncthreads();
    int bad = 0;
    for (int i = threadIdx.x; i < n / 2; i += blockDim.x)
        if (idxp[2 * i + 1] != 0) bad = 1;
    if (bad) atomicExch(&sbad, 1);
    __syncthreads();
    if (threadIdx.x == 0) g_is64 = sbad ? 0 : 1;
    if (threadIdx.x < LNUM) g_cnt[threadIdx.x] = 0;
}

// ---------------- 1) group tokens by expert + zero g_xa ----------------
__global__ void k_group(const int* __restrict__ idxp) {
    int t = blockIdx.x * blockDim.x + threadIdx.x;
    if (t < MDIM) {
        float4* z = (float4*)(g_xa + t * 32);
#pragma unroll
        for (int q = 0; q < 8; q++) z[q] = make_float4(0.f, 0.f, 0.f, 0.f);
        int l = load_idx(idxp, t);
        int pos = atomicAdd(&g_cnt[l], 1);
        g_list[l * MDIM + pos] = t;
    }
}

// ---------------- 2) convert x -> fragment-permuted fp16 ----------------
__global__ __launch_bounds__(256) void k_convx(const float* __restrict__ x) {
    __shared__ float s[16][260];
    const int tid = threadIdx.x;
    const int mt = blockIdx.x;
    const int m0 = mt * 16, k0 = blockIdx.y * 256;
#pragma unroll
    for (int p = 0; p < 4; p++) {
        int idx = tid + p * 256;
        int row = idx >> 6, c4 = (idx & 63) * 4;
        float4 v = *(const float4*)(x + (size_t)(m0 + row) * KDIM + k0 + c4);
        s[row][c4] = v.x; s[row][c4 + 1] = v.y; s[row][c4 + 2] = v.z; s[row][c4 + 3] = v.w;
    }
    __syncthreads();
    const int w = tid >> 5, lane = tid & 31;
    const int g = lane >> 2, tg2 = (lane & 3) * 2;
#pragma unroll
    for (int q = 0; q < 2; q++) {
        int ktl = w * 2 + q;
        int kc = ktl * 16;
        uint32_t a0 = pack_h2(s[g][kc + tg2], s[g][kc + tg2 + 1]);
        uint32_t a1 = pack_h2(s[g + 8][kc + tg2], s[g + 8][kc + tg2 + 1]);
        uint32_t a2 = pack_h2(s[g][kc + tg2 + 8], s[g][kc + tg2 + 9]);
        uint32_t a3 = pack_h2(s[g + 8][kc + tg2 + 8], s[g + 8][kc + tg2 + 9]);
        int ktg = blockIdx.y * 16 + ktl;
        g_xt[((size_t)mt * KT + ktg) * 32 + lane] = make_uint4(a0, a1, a2, a3);
    }
}

// ---------------- 3) convert W -> fragment-permuted fp16 (scaled x256) ------
__global__ __launch_bounds__(256) void k_convw(const float* __restrict__ W) {
    __shared__ float s[16][260];
    const int tid = threadIdx.x;
    const int n0 = blockIdx.x * 16, k0 = blockIdx.y * 256;
#pragma unroll
    for (int p = 0; p < 4; p++) {
        int idx = tid + p * 256;
        int row = idx >> 6, c4 = (idx & 63) * 4;
        float4 v = *(const float4*)(W + (size_t)(n0 + row) * KDIM + k0 + c4);
        s[row][c4] = v.x * WSCALE; s[row][c4 + 1] = v.y * WSCALE;
        s[row][c4 + 2] = v.z * WSCALE; s[row][c4 + 3] = v.w * WSCALE;
    }
    __syncthreads();
    const int w = tid >> 5, lane = tid & 31;
    const int g = lane >> 2, tg2 = (lane & 3) * 2;
#pragma unroll
    for (int q = 0; q < 2; q++) {
        int ktl = w * 2 + q;
        int kc = ktl * 16;
        int ktg = blockIdx.y * 16 + ktl;
#pragma unroll
        for (int nsub = 0; nsub < 2; nsub++) {
            uint32_t b0 = pack_h2(s[nsub * 8 + g][kc + tg2], s[nsub * 8 + g][kc + tg2 + 1]);
            uint32_t b1 = pack_h2(s[nsub * 8 + g][kc + tg2 + 8], s[nsub * 8 + g][kc + tg2 + 9]);
            int nt = blockIdx.x * 2 + nsub;
            g_wt[((size_t)nt * KT + ktg) * 32 + lane] = make_uint2(b0, b1);
        }
    }
}

// ---------------- 4) xa: split-K, 4 indep accumulator chains ----------------
// grid (k-chunk 0..15, expert 0..15) = 256 CTAs. A chunk in smem once; each
// warp streams tokens with NO barriers; 4 accumulators cap dep chain at 32.
__global__ __launch_bounds__(256) void k_xa3(const float* __restrict__ x,
                                             const float* __restrict__ A) {
    __shared__ float As[XKC][33];
    const int l = blockIdx.y;
    const int d0 = blockIdx.x * XKC;
    const int tid = threadIdx.x, w = tid >> 5, lane = tid & 31;

    // stage A[l, d0:d0+128, 0:32]
#pragma unroll
    for (int j = 0; j < 16; j++) {
        int idx = tid + j * 256;
        int dd = idx >> 5, c = idx & 31;
        As[dd][c] = A[((size_t)l * KDIM + d0 + dd) * 32 + c];
    }
    __syncthreads();

    const int cnt = g_cnt[l];
#pragma unroll 1
    for (int i = w; i < cnt; i += 8) {
        const int t = g_list[l * MDIM + i];
        float4 v = ((const float4*)(x + (size_t)t * KDIM + d0))[lane];
        float a0 = 0.f, a1 = 0.f, a2 = 0.f, a3 = 0.f;
#pragma unroll
        for (int sl = 0; sl < 32; sl++) {
            float b0 = __shfl_sync(0xffffffffu, v.x, sl);
            float b1 = __shfl_sync(0xffffffffu, v.y, sl);
            float b2 = __shfl_sync(0xffffffffu, v.z, sl);
            float b3 = __shfl_sync(0xffffffffu, v.w, sl);
            a0 += b0 * As[sl * 4 + 0][lane];
            a1 += b1 * As[sl * 4 + 1][lane];
            a2 += b2 * As[sl * 4 + 2][lane];
            a3 += b3 * As[sl * 4 + 3][lane];
        }
        atomicAdd(&g_xa[t * 32 + lane], (a0 + a1) + (a2 + a3));
    }
}

// ---------------- 5) fp16 mma.sync GEMM, occ=2 ----------------
__global__ __launch_bounds__(256, 2) void k_gemm(float* __restrict__ out) {
    extern __shared__ char dyn[];
    const uint32_t dbase = smem_u32(dyn);

    const int tid = threadIdx.x;
    const int wid = tid >> 5;
    const int lane = tid & 31;
    const int mt0 = blockIdx.x * 8;
    const int nt0 = blockIdx.y * 16;
    const int mhalf = wid & 1;
    const int nq = wid >> 1;

    const char* gA = (const char*)g_xt;
    const char* gB = (const char*)g_wt;

    auto issue_stage = [&](int s, int b) {
        const uint32_t abase = dbase + b * STAGE_BYTES;
        const uint32_t bbase = abase + STAGE_A;
#pragma unroll
        for (int j = 0; j < 4; j++) {
            int c = tid + j * 256;
            int mtl = c >> 7, r = c & 127;
            const char* src = gA + (size_t)(mt0 + mtl) * XT_ROW + s * 2048 + r * 16;
            cpasync16(abase + mtl * 2048 + r * 16, src);
        }
#pragma unroll
        for (int j = 0; j < 4; j++) {
            int c = tid + j * 256;
            int ntl = c >> 6, r = c & 63;
            const char* src = gB + (size_t)(nt0 + ntl) * WT_ROW + s * 1024 + r * 16;
            cpasync16(bbase + ntl * 1024 + r * 16, src);
        }
        cp_commit();
    };

    float c[4][4][4];
#pragma unroll
    for (int i = 0; i < 4; i++)
#pragma unroll
        for (int j = 0; j < 4; j++)
#pragma unroll
            for (int q = 0; q < 4; q++) c[i][j][q] = 0.f;

    issue_stage(0, 0);
    issue_stage(1, 1);

#pragma unroll 1
    for (int s = 0; s < NS; s++) {
        if (s < NS - 1) cp_wait<1>();
        else cp_wait<0>();
        __syncthreads();

        if (s + 2 < NS) issue_stage(s + 2, (s + 2) % 3);

        const char* sa = dyn + (s % 3) * STAGE_BYTES;
        const char* sb = sa + STAGE_A;

#pragma unroll
        for (int ktl = 0; ktl < 4; ktl++) {
            uint4 a[4];
            uint2 bfr[4];
#pragma unroll
            for (int i = 0; i < 4; i++) {
                int mtl = mhalf * 4 + i;
                a[i] = *(const uint4*)(sa + mtl * 2048 + ktl * 512 + lane * 16);
            }
#pragma unroll
            for (int j = 0; j < 4; j++) {
                int ntl = nq * 4 + j;
                bfr[j] = *(const uint2*)(sb + ntl * 1024 + ktl * 256 + lane * 8);
            }
#pragma unroll
            for (int i = 0; i < 4; i++)
#pragma unroll
                for (int j = 0; j < 4; j++) {
                    asm volatile(
                        "mma.sync.aligned.m16n8k16.row.col.f32.f16.f16.f32 "
                        "{%0,%1,%2,%3}, {%4,%5,%6,%7}, {%8,%9}, {%0,%1,%2,%3};\n"
                        : "+f"(c[i][j][0]), "+f"(c[i][j][1]),
                          "+f"(c[i][j][2]), "+f"(c[i][j][3])
                        : "r"(a[i].x), "r"(a[i].y), "r"(a[i].z), "r"(a[i].w),
                          "r"(bfr[j].x), "r"(bfr[j].y));
                }
        }
    }

    const int g = lane >> 2, tg = lane & 3;
    const int m0 = blockIdx.x * TILE_M, n0 = blockIdx.y * TILE_N;
#pragma unroll
    for (int i = 0; i < 4; i++) {
        int row0 = m0 + mhalf * 64 + i * 16 + g;
#pragma unroll
        for (int j = 0; j < 4; j++) {
            int col = n0 + nq * 32 + j * 8 + tg * 2;
            *(float2*)(out + (size_t)row0 * NDIM + col) =
                make_float2(c[i][j][0] * OSCALE, c[i][j][1] * OSCALE);
            *(float2*)(out + (size_t)(row0 + 8) * NDIM + col) =
                make_float2(c[i][j][2] * OSCALE, c[i][j][3] * OSCALE);
        }
    }
}

// ---------------- 6) rank-16 delta: smem-staged, 4 tokens in flight ---------
__global__ __launch_bounds__(128) void k_delta(const float* __restrict__ B,
                                               float* __restrict__ out) {
    const int l = blockIdx.y;
    const int n0 = blockIdx.x * DN;
    const int h = (n0 >= HALF_N) ? 16 : 0;
    const int tid = threadIdx.x;

    __shared__ float4 Bs[RNK][DN / 4];
    __shared__ float  xas[128][17];
    __shared__ int    stok[128];

    for (int i = tid; i < RNK * (DN / 4); i += 128) {
        int r = i >> 7, cc = i & 127;
        Bs[r][cc] = *(const float4*)(B + ((size_t)l * RNK + r) * NDIM + n0 + cc * 4);
    }
    const int cnt = g_cnt[l];

    for (int ib = 0; ib < cnt; ib += 128) {
        const int bc = min(128, cnt - ib);
        __syncthreads();
        if (tid < bc) stok[tid] = g_list[l * MDIM + ib + tid];
        __syncthreads();
        for (int i = tid; i < bc * 16; i += 128) {
            int s = i >> 4, r = i & 15;
            xas[s][r] = g_xa[stok[s] * 32 + h + r];
        }
        __syncthreads();

#pragma unroll 1
        for (int i0 = 0; i0 < bc; i0 += 4) {
            float4 acc0 = make_float4(0.f, 0.f, 0.f, 0.f);
            float4 acc1 = acc0, acc2 = acc0, acc3 = acc0;
#pragma unroll
            for (int r = 0; r < RNK; r++) {
                float4 b4 = Bs[r][tid];
                float s0 = xas[i0 + 0][r];
                float s1 = xas[(i0 + 1) & 127][r];
                float s2 = xas[(i0 + 2) & 127][r];
                float s3 = xas[(i0 + 3) & 127][r];
                acc0.x += s0 * b4.x; acc0.y += s0 * b4.y; acc0.z += s0 * b4.z; acc0.w += s0 * b4.w;
                acc1.x += s1 * b4.x; acc1.y += s1 * b4.y; acc1.z += s1 * b4.z; acc1.w += s1 * b4.w;
                acc2.x += s2 * b4.x; acc2.y += s2 * b4.y; acc2.z += s2 * b4.z; acc2.w += s2 * b4.w;
                acc3.x += s3 * b4.x; acc3.y += s3 * b4.y; acc3.z += s3 * b4.z; acc3.w += s3 * b4.w;
            }
            float4 accs[4] = {acc0, acc1, acc2, acc3};
#pragma unroll
            for (int tk = 0; tk < 4; tk++) {
                int ii = i0 + tk;
                if (ii < bc) {
                    float4* op = (float4*)(out + (size_t)stok[ii] * NDIM + n0 + tid * 4);
                    float4 v = *op;
                    v.x += accs[tk].x; v.y += accs[tk].y;
                    v.z += accs[tk].z; v.w += accs[tk].w;
                    *op = v;
                }
            }
        }
    }
}

// ---------------- launch (k_xa3 at capture index 3) ----------------
extern "C" void kernel_launch(void* const* d_in, const int* in_sizes, int n_in,
                              void* d_out, int out_size) {
    const float* x = (const float*)d_in[0];
    const float* W = (const float*)d_in[1];
    const float* A = (const float*)d_in[2];
    const float* B = (const float*)d_in[3];
    const int* idxp = (const int*)d_in[4];
    float* out = (float*)d_out;

    cudaFuncSetAttribute(k_gemm, cudaFuncAttributeMaxDynamicSharedMemorySize, SMEM_DYN);

    k_detect<<<1, 256>>>(idxp, MDIM);
    k_group<<<8, 256>>>(idxp);
    k_convx<<<dim3(MDIM / 16, KDIM / 256), 256>>>(x);
    k_xa3<<<dim3(KDIM / XKC, LNUM), 256>>>(x, A);
    k_convw<<<dim3(NDIM / 16, KDIM / 256), 256>>>(W);
    k_gemm<<<dim3(MDIM / TILE_M, NDIM / TILE_N), 256, SMEM_DYN>>>(out);
    k_delta<<<dim3(NDIM / DN, LNUM), 128>>>(B, out);
}

// round 16
// speedup vs baseline: 2.8345x; 1.1393x over previous
#include <cuda_runtime.h>
#include <cuda_fp16.h>
#include <cstdint>

#define MDIM 2048
#define NDIM 11264
#define KDIM 2048
#define LNUM 16
#define RNK 16
#define HALF_N 5632

// GEMM tiling: CTA 128m x 128n, fp16 m16n8k16, BK=64, 3-buf pipeline, occ 2
#define TILE_M 128
#define TILE_N 128
#define NS (KDIM / 64)                   // 32 stages
#define STAGE_A (8 * 4 * 512)            // 16384 B
#define STAGE_B (16 * 4 * 256)           // 16384 B
#define STAGE_BYTES (STAGE_A + STAGE_B)  // 32768
#define NBUF 3
#define SMEM_DYN (NBUF * STAGE_BYTES)    // 98304

#define KT (KDIM / 16)                   // 128 k-tiles
#define XT_ROW (KT * 512)
#define WT_ROW (KT * 256)
#define WSCALE 256.0f
#define OSCALE 0.00390625f

#define DN 512                           // delta: cols per block
#define XKC 128                          // xa: k-chunk size (16 chunks)

// ---------------- device scratch ----------------
__device__ uint4 g_xt[(size_t)(MDIM / 16) * KT * 32];
__device__ uint2 g_wt[(size_t)(NDIM / 8) * KT * 32];
__device__ float g_xa[MDIM * 32];
__device__ int   g_cnt[LNUM];
__device__ int   g_list[LNUM * MDIM];
__device__ int   g_is64;

__device__ __forceinline__ int load_idx(const int* p, int t) {
    return g_is64 ? p[2 * t] : p[t];
}

// ---------------- helpers ----------------
__device__ __forceinline__ uint32_t smem_u32(const void* p) {
    uint32_t a;
    asm("{ .reg .u64 t; cvta.to.shared.u64 t, %1; cvt.u32.u64 %0, t; }" : "=r"(a) : "l"(p));
    return a;
}
__device__ __forceinline__ void cpasync16(uint32_t dst, const void* src) {
    asm volatile("cp.async.cg.shared.global [%0], [%1], 16;" :: "r"(dst), "l"(src));
}
__device__ __forceinline__ void cp_commit() {
    asm volatile("cp.async.commit_group;" ::: "memory");
}
template <int N> __device__ __forceinline__ void cp_wait() {
    asm volatile("cp.async.wait_group %0;" :: "n"(N) : "memory");
}
__device__ __forceinline__ uint32_t pack_h2(float lo, float hi) {
    __half2 h = __floats2half2_rn(lo, hi);
    return *(uint32_t*)&h;
}

// ---------------- 0) dtype detect + counter zero ----------------
__global__ void k_detect(const int* __restrict__ idxp, int n) {
    __shared__ int sbad;
    if (threadIdx.x == 0) sbad = 0;
    __syncthreads();
    int bad = 0;
    for (int i = threadIdx.x; i < n / 2; i += blockDim.x)
        if (idxp[2 * i + 1] != 0) bad = 1;
    if (bad) atomicExch(&sbad, 1);
    __syncthreads();
    if (threadIdx.x == 0) g_is64 = sbad ? 0 : 1;
    if (threadIdx.x < LNUM) g_cnt[threadIdx.x] = 0;
}

// ---------------- 1) group tokens by expert + zero g_xa ----------------
__global__ void k_group(const int* __restrict__ idxp) {
    int t = blockIdx.x * blockDim.x + threadIdx.x;
    if (t < MDIM) {
        float4* z = (float4*)(g_xa + t * 32);
#pragma unroll
        for (int q = 0; q < 8; q++) z[q] = make_float4(0.f, 0.f, 0.f, 0.f);
        int l = load_idx(idxp, t);
        int pos = atomicAdd(&g_cnt[l], 1);
        g_list[l * MDIM + pos] = t;
    }
}

// ---------------- 2) convert x -> fragment-permuted fp16 ----------------
__global__ __launch_bounds__(256) void k_convx(const float* __restrict__ x) {
    __shared__ float s[16][260];
    const int tid = threadIdx.x;
    const int mt = blockIdx.x;
    const int m0 = mt * 16, k0 = blockIdx.y * 256;
#pragma unroll
    for (int p = 0; p < 4; p++) {
        int idx = tid + p * 256;
        int row = idx >> 6, c4 = (idx & 63) * 4;
        float4 v = *(const float4*)(x + (size_t)(m0 + row) * KDIM + k0 + c4);
        s[row][c4] = v.x; s[row][c4 + 1] = v.y; s[row][c4 + 2] = v.z; s[row][c4 + 3] = v.w;
    }
    __syncthreads();
    const int w = tid >> 5, lane = tid & 31;
    const int g = lane >> 2, tg2 = (lane & 3) * 2;
#pragma unroll
    for (int q = 0; q < 2; q++) {
        int ktl = w * 2 + q;
        int kc = ktl * 16;
        uint32_t a0 = pack_h2(s[g][kc + tg2], s[g][kc + tg2 + 1]);
        uint32_t a1 = pack_h2(s[g + 8][kc + tg2], s[g + 8][kc + tg2 + 1]);
        uint32_t a2 = pack_h2(s[g][kc + tg2 + 8], s[g][kc + tg2 + 9]);
        uint32_t a3 = pack_h2(s[g + 8][kc + tg2 + 8], s[g + 8][kc + tg2 + 9]);
        int ktg = blockIdx.y * 16 + ktl;
        g_xt[((size_t)mt * KT + ktg) * 32 + lane] = make_uint4(a0, a1, a2, a3);
    }
}

// ---------------- 3) convert W -> fragment-permuted fp16 (scaled x256) ------
__global__ __launch_bounds__(256) void k_convw(const float* __restrict__ W) {
    __shared__ float s[16][260];
    const int tid = threadIdx.x;
    const int n0 = blockIdx.x * 16, k0 = blockIdx.y * 256;
#pragma unroll
    for (int p = 0; p < 4; p++) {
        int idx = tid + p * 256;
        int row = idx >> 6, c4 = (idx & 63) * 4;
        float4 v = *(const float4*)(W + (size_t)(n0 + row) * KDIM + k0 + c4);
        s[row][c4] = v.x * WSCALE; s[row][c4 + 1] = v.y * WSCALE;
        s[row][c4 + 2] = v.z * WSCALE; s[row][c4 + 3] = v.w * WSCALE;
    }
    __syncthreads();
    const int w = tid >> 5, lane = tid & 31;
    const int g = lane >> 2, tg2 = (lane & 3) * 2;
#pragma unroll
    for (int q = 0; q < 2; q++) {
        int ktl = w * 2 + q;
        int kc = ktl * 16;
        int ktg = blockIdx.y * 16 + ktl;
#pragma unroll
        for (int nsub = 0; nsub < 2; nsub++) {
            uint32_t b0 = pack_h2(s[nsub * 8 + g][kc + tg2], s[nsub * 8 + g][kc + tg2 + 1]);
            uint32_t b1 = pack_h2(s[nsub * 8 + g][kc + tg2 + 8], s[nsub * 8 + g][kc + tg2 + 9]);
            int nt = blockIdx.x * 2 + nsub;
            g_wt[((size_t)nt * KT + ktg) * 32 + lane] = make_uint2(b0, b1);
        }
    }
}

// ---------------- 4) xa: split-K, 2-token interleave, As reuse --------------
// grid (k-chunk 0..15, expert 0..15). 8 indep chains per warp-iteration; the
// As smem loads are shared between the token pair.
__global__ __launch_bounds__(256) void k_xa3(const float* __restrict__ x,
                                             const float* __restrict__ A) {
    __shared__ float As[XKC][33];
    const int l = blockIdx.y;
    const int d0 = blockIdx.x * XKC;
    const int tid = threadIdx.x, w = tid >> 5, lane = tid & 31;

#pragma unroll
    for (int j = 0; j < 16; j++) {
        int idx = tid + j * 256;
        int dd = idx >> 5, c = idx & 31;
        As[dd][c] = A[((size_t)l * KDIM + d0 + dd) * 32 + c];
    }
    __syncthreads();

    const int cnt = g_cnt[l];
#pragma unroll 1
    for (int i = w * 2; i < cnt; i += 16) {
        const int t0 = g_list[l * MDIM + i];
        const bool has2 = (i + 1 < cnt);
        const int t1 = has2 ? g_list[l * MDIM + i + 1] : t0;
        float4 v0 = ((const float4*)(x + (size_t)t0 * KDIM + d0))[lane];
        float4 v1 = ((const float4*)(x + (size_t)t1 * KDIM + d0))[lane];
        float a00 = 0.f, a01 = 0.f, a02 = 0.f, a03 = 0.f;
        float a10 = 0.f, a11 = 0.f, a12 = 0.f, a13 = 0.f;
#pragma unroll
        for (int sl = 0; sl < 32; sl++) {
            float s0 = As[sl * 4 + 0][lane];
            float s1 = As[sl * 4 + 1][lane];
            float s2 = As[sl * 4 + 2][lane];
            float s3 = As[sl * 4 + 3][lane];
            a00 += __shfl_sync(0xffffffffu, v0.x, sl) * s0;
            a01 += __shfl_sync(0xffffffffu, v0.y, sl) * s1;
            a02 += __shfl_sync(0xffffffffu, v0.z, sl) * s2;
            a03 += __shfl_sync(0xffffffffu, v0.w, sl) * s3;
            a10 += __shfl_sync(0xffffffffu, v1.x, sl) * s0;
            a11 += __shfl_sync(0xffffffffu, v1.y, sl) * s1;
            a12 += __shfl_sync(0xffffffffu, v1.z, sl) * s2;
            a13 += __shfl_sync(0xffffffffu, v1.w, sl) * s3;
        }
        atomicAdd(&g_xa[t0 * 32 + lane], (a00 + a01) + (a02 + a03));
        if (has2)
            atomicAdd(&g_xa[t1 * 32 + lane], (a10 + a11) + (a12 + a13));
    }
}

// ---------------- 5) fp16 mma.sync GEMM, occ=2 ----------------
__global__ __launch_bounds__(256, 2) void k_gemm(float* __restrict__ out) {
    extern __shared__ char dyn[];
    const uint32_t dbase = smem_u32(dyn);

    const int tid = threadIdx.x;
    const int wid = tid >> 5;
    const int lane = tid & 31;
    const int mt0 = blockIdx.x * 8;
    const int nt0 = blockIdx.y * 16;
    const int mhalf = wid & 1;
    const int nq = wid >> 1;

    const char* gA = (const char*)g_xt;
    const char* gB = (const char*)g_wt;

    auto issue_stage = [&](int s, int b) {
        const uint32_t abase = dbase + b * STAGE_BYTES;
        const uint32_t bbase = abase + STAGE_A;
#pragma unroll
        for (int j = 0; j < 4; j++) {
            int c = tid + j * 256;
            int mtl = c >> 7, r = c & 127;
            const char* src = gA + (size_t)(mt0 + mtl) * XT_ROW + s * 2048 + r * 16;
            cpasync16(abase + mtl * 2048 + r * 16, src);
        }
#pragma unroll
        for (int j = 0; j < 4; j++) {
            int c = tid + j * 256;
            int ntl = c >> 6, r = c & 63;
            const char* src = gB + (size_t)(nt0 + ntl) * WT_ROW + s * 1024 + r * 16;
            cpasync16(bbase + ntl * 1024 + r * 16, src);
        }
        cp_commit();
    };

    float c[4][4][4];
#pragma unroll
    for (int i = 0; i < 4; i++)
#pragma unroll
        for (int j = 0; j < 4; j++)
#pragma unroll
            for (int q = 0; q < 4; q++) c[i][j][q] = 0.f;

    issue_stage(0, 0);
    issue_stage(1, 1);

#pragma unroll 1
    for (int s = 0; s < NS; s++) {
        if (s < NS - 1) cp_wait<1>();
        else cp_wait<0>();
        __syncthreads();

        if (s + 2 < NS) issue_stage(s + 2, (s + 2) % 3);

        const char* sa = dyn + (s % 3) * STAGE_BYTES;
        const char* sb = sa + STAGE_A;

#pragma unroll
        for (int ktl = 0; ktl < 4; ktl++) {
            uint4 a[4];
            uint2 bfr[4];
#pragma unroll
            for (int i = 0; i < 4; i++) {
                int mtl = mhalf * 4 + i;
                a[i] = *(const uint4*)(sa + mtl * 2048 + ktl * 512 + lane * 16);
            }
#pragma unroll
            for (int j = 0; j < 4; j++) {
                int ntl = nq * 4 + j;
                bfr[j] = *(const uint2*)(sb + ntl * 1024 + ktl * 256 + lane * 8);
            }
#pragma unroll
            for (int i = 0; i < 4; i++)
#pragma unroll
                for (int j = 0; j < 4; j++) {
                    asm volatile(
                        "mma.sync.aligned.m16n8k16.row.col.f32.f16.f16.f32 "
                        "{%0,%1,%2,%3}, {%4,%5,%6,%7}, {%8,%9}, {%0,%1,%2,%3};\n"
                        : "+f"(c[i][j][0]), "+f"(c[i][j][1]),
                          "+f"(c[i][j][2]), "+f"(c[i][j][3])
                        : "r"(a[i].x), "r"(a[i].y), "r"(a[i].z), "r"(a[i].w),
                          "r"(bfr[j].x), "r"(bfr[j].y));
                }
        }
    }

    const int g = lane >> 2, tg = lane & 3;
    const int m0 = blockIdx.x * TILE_M, n0 = blockIdx.y * TILE_N;
#pragma unroll
    for (int i = 0; i < 4; i++) {
        int row0 = m0 + mhalf * 64 + i * 16 + g;
#pragma unroll
        for (int j = 0; j < 4; j++) {
            int col = n0 + nq * 32 + j * 8 + tg * 2;
            *(float2*)(out + (size_t)row0 * NDIM + col) =
                make_float2(c[i][j][0] * OSCALE, c[i][j][1] * OSCALE);
            *(float2*)(out + (size_t)(row0 + 8) * NDIM + col) =
                make_float2(c[i][j][2] * OSCALE, c[i][j][3] * OSCALE);
        }
    }
}

// ---------------- 6) rank-16 delta: smem-staged, token-split grid.z ---------
__global__ __launch_bounds__(128) void k_delta(const float* __restrict__ B,
                                               float* __restrict__ out) {
    const int l = blockIdx.y;
    const int n0 = blockIdx.x * DN;
    const int h = (n0 >= HALF_N) ? 16 : 0;
    const int tid = threadIdx.x;

    __shared__ float4 Bs[RNK][DN / 4];
    __shared__ float  xas[128][17];
    __shared__ int    stok[128];

    for (int i = tid; i < RNK * (DN / 4); i += 128) {
        int r = i >> 7, cc = i & 127;
        Bs[r][cc] = *(const float4*)(B + ((size_t)l * RNK + r) * NDIM + n0 + cc * 4);
    }
    const int cnt = g_cnt[l];
    const int halfc = (cnt + 1) >> 1;
    const int start = blockIdx.z * halfc;
    const int end = min(cnt, start + halfc);

    for (int ib = start; ib < end; ib += 128) {
        const int bc = min(128, end - ib);
        __syncthreads();
        if (tid < bc) stok[tid] = g_list[l * MDIM + ib + tid];
        __syncthreads();
        for (int i = tid; i < bc * 16; i += 128) {
            int s = i >> 4, r = i & 15;
            xas[s][r] = g_xa[stok[s] * 32 + h + r];
        }
        __syncthreads();

#pragma unroll 1
        for (int i0 = 0; i0 < bc; i0 += 4) {
            float4 acc0 = make_float4(0.f, 0.f, 0.f, 0.f);
            float4 acc1 = acc0, acc2 = acc0, acc3 = acc0;
#pragma unroll
            for (int r = 0; r < RNK; r++) {
                float4 b4 = Bs[r][tid];
                float s0 = xas[i0 + 0][r];
                float s1 = xas[(i0 + 1) & 127][r];
                float s2 = xas[(i0 + 2) & 127][r];
                float s3 = xas[(i0 + 3) & 127][r];
                acc0.x += s0 * b4.x; acc0.y += s0 * b4.y; acc0.z += s0 * b4.z; acc0.w += s0 * b4.w;
                acc1.x += s1 * b4.x; acc1.y += s1 * b4.y; acc1.z += s1 * b4.z; acc1.w += s1 * b4.w;
                acc2.x += s2 * b4.x; acc2.y += s2 * b4.y; acc2.z += s2 * b4.z; acc2.w += s2 * b4.w;
                acc3.x += s3 * b4.x; acc3.y += s3 * b4.y; acc3.z += s3 * b4.z; acc3.w += s3 * b4.w;
            }
            float4 accs[4] = {acc0, acc1, acc2, acc3};
#pragma unroll
            for (int tk = 0; tk < 4; tk++) {
                int ii = i0 + tk;
                if (ii < bc) {
                    float4* op = (float4*)(out + (size_t)stok[ii] * NDIM + n0 + tid * 4);
                    float4 v = *op;
                    v.x += accs[tk].x; v.y += accs[tk].y;
                    v.z += accs[tk].z; v.w += accs[tk].w;
                    *op = v;
                }
            }
        }
    }
}

// ---------------- launch (k_gemm at capture index 3) ----------------
extern "C" void kernel_launch(void* const* d_in, const int* in_sizes, int n_in,
                              void* d_out, int out_size) {
    const float* x = (const float*)d_in[0];
    const float* W = (const float*)d_in[1];
    const float* A = (const float*)d_in[2];
    const float* B = (const float*)d_in[3];
    const int* idxp = (const int*)d_in[4];
    float* out = (float*)d_out;

    cudaFuncSetAttribute(k_gemm, cudaFuncAttributeMaxDynamicSharedMemorySize, SMEM_DYN);

    k_detect<<<1, 256>>>(idxp, MDIM);
    k_convx<<<dim3(MDIM / 16, KDIM / 256), 256>>>(x);
    k_convw<<<dim3(NDIM / 16, KDIM / 256), 256>>>(W);
    k_gemm<<<dim3(MDIM / TILE_M, NDIM / TILE_N), 256, SMEM_DYN>>>(out);
    k_group<<<8, 256>>>(idxp);
    k_xa3<<<dim3(KDIM / XKC, LNUM), 256>>>(x, A);
    k_delta<<<dim3(NDIM / DN, LNUM, 2), 128>>>(B, out);
}